// round 8
// baseline (speedup 1.0000x reference)
#include <cuda_runtime.h>
#include <cuda_bf16.h>
#include <cstdint>
#include <math.h>

#define EMBED  1024
#define NHEADS 16
#define HDIM   64
#define NB     2
#define NSEQ   2048
#define MTOT   (NB*NSEQ)          // 4096
#define GEMM_K 1024
#define ATTN_SCALE 0.125f

// ---------------- scratch (__device__ globals) ------------------------------
__device__ __nv_bfloat16 g_Xh[MTOT*EMBED],      g_Xl[MTOT*EMBED];
__device__ __nv_bfloat16 g_Wqh[3*EMBED*EMBED],  g_Wql[3*EMBED*EMBED];
__device__ __nv_bfloat16 g_Woh[EMBED*EMBED],    g_Wol[EMBED*EMBED];
__device__ __nv_bfloat16 g_Qh[NB*NHEADS*NSEQ*HDIM], g_Ql[NB*NHEADS*NSEQ*HDIM];
__device__ __nv_bfloat16 g_Kh[NB*NHEADS*NSEQ*HDIM], g_Kl[NB*NHEADS*NSEQ*HDIM];
__device__ __nv_bfloat16 g_Vh[NB*NHEADS*NSEQ*HDIM], g_Vl[NB*NHEADS*NSEQ*HDIM];
__device__ __nv_bfloat16 g_AOh[MTOT*EMBED],     g_AOl[MTOT*EMBED];

// ---------------- helpers ---------------------------------------------------
__device__ __forceinline__ uint32_t smem_u32(const void* p) {
    uint32_t a;
    asm("{ .reg .u64 t; cvta.to.shared.u64 t, %1; cvt.u32.u64 %0, t; }"
        : "=r"(a) : "l"(p));
    return a;
}
__device__ __forceinline__ void ldsm4(uint32_t addr, uint32_t* r) {
    asm volatile("ldmatrix.sync.aligned.m8n8.x4.shared.b16 {%0,%1,%2,%3}, [%4];"
        : "=r"(r[0]), "=r"(r[1]), "=r"(r[2]), "=r"(r[3]) : "r"(addr));
}
__device__ __forceinline__ void ldsm4t(uint32_t addr, uint32_t* r) {
    asm volatile("ldmatrix.sync.aligned.m8n8.x4.trans.shared.b16 {%0,%1,%2,%3}, [%4];"
        : "=r"(r[0]), "=r"(r[1]), "=r"(r[2]), "=r"(r[3]) : "r"(addr));
}
__device__ __forceinline__ void mma_bf16(float* d, const uint32_t* a, const uint32_t* b) {
    asm volatile(
        "mma.sync.aligned.m16n8k16.row.col.f32.bf16.bf16.f32 "
        "{%0,%1,%2,%3},{%4,%5,%6,%7},{%8,%9},{%0,%1,%2,%3};"
        : "+f"(d[0]), "+f"(d[1]), "+f"(d[2]), "+f"(d[3])
        : "r"(a[0]), "r"(a[1]), "r"(a[2]), "r"(a[3]), "r"(b[0]), "r"(b[1]));
}
__device__ __forceinline__ void cp16(uint32_t s, const void* g) {
    asm volatile("cp.async.cg.shared.global [%0], [%1], 16;" :: "r"(s), "l"(g));
}
#define CP_COMMIT() asm volatile("cp.async.commit_group;" ::: "memory")
#define CP_WAIT0()  asm volatile("cp.async.wait_group 0;" ::: "memory")
#define CP_WAIT1()  asm volatile("cp.async.wait_group 1;" ::: "memory")

__device__ __forceinline__ uint32_t bits_bf162(__nv_bfloat162 h) {
    return *reinterpret_cast<uint32_t*>(&h);
}
__device__ __forceinline__ uint32_t hipack(float x, float y) {
    return (__float_as_uint(x) >> 16) | (__float_as_uint(y) & 0xffff0000u);
}
__device__ __forceinline__ uint32_t lopack(float x, float y) {
    float lx = x - __uint_as_float(__float_as_uint(x) & 0xffff0000u);
    float ly = y - __uint_as_float(__float_as_uint(y) & 0xffff0000u);
    return bits_bf162(__floats2bfloat162_rn(lx, ly));
}
__device__ __forceinline__ void cvt_hl(float4 v, uint2& h, uint2& l) {
    h.x = hipack(v.x, v.y); h.y = hipack(v.z, v.w);
    l.x = lopack(v.x, v.y); l.y = lopack(v.z, v.w);
}
// 128B-row swizzle (flash tiles): 16B chunk XOR row%8
__device__ __forceinline__ uint32_t swz128(int row, int chunk) {
    return (uint32_t)(row * 128 + ((chunk ^ (row & 7)) << 4));
}
// 32B-row GEMM tile swizzle: chunk(0/1) XOR (row>>2)&1
__device__ __forceinline__ uint32_t tile_off(int r, int chunk) {
    return (uint32_t)(r * 32 + ((chunk ^ ((r >> 2) & 1)) << 4));
}

// ---------------------------------------------------------------------------
// Pre-kernels: one-time conversions
// ---------------------------------------------------------------------------
__global__ void convert_hl_kernel(const float* __restrict__ S,
                                  __nv_bfloat16* __restrict__ Dh,
                                  __nv_bfloat16* __restrict__ Dl)
{
    int i = blockIdx.x * blockDim.x + threadIdx.x;   // float4 index
    float4 v = ((const float4*)S)[i];
    uint2 h, l; cvt_hl(v, h, l);
    ((uint2*)Dh)[i] = h;
    ((uint2*)Dl)[i] = l;
}

// src[K][N] f32 -> dst[N][K] bf16 hi/lo
__global__ void transpose_hl_kernel(const float* __restrict__ S,
                                    __nv_bfloat16* __restrict__ Dh,
                                    __nv_bfloat16* __restrict__ Dl,
                                    int K, int N)
{
    __shared__ float t[32][33];
    int bx = blockIdx.x * 32;   // N dim
    int by = blockIdx.y * 32;   // K dim
    int tx = threadIdx.x, ty = threadIdx.y;
#pragma unroll
    for (int j = 0; j < 32; j += 8)
        t[ty + j][tx] = S[(size_t)(by + ty + j) * N + bx + tx];
    __syncthreads();
#pragma unroll
    for (int j = 0; j < 32; j += 8) {
        float v = t[tx][ty + j];
        size_t idx = (size_t)(bx + ty + j) * K + by + tx;
        uint32_t u = __float_as_uint(v);
        ((uint16_t*)Dh)[idx] = (uint16_t)(u >> 16);
        float lr = v - __uint_as_float(u & 0xffff0000u);
        __nv_bfloat16 lb = __float2bfloat16(lr);
        ((uint16_t*)Dl)[idx] = *reinterpret_cast<uint16_t*>(&lb);
    }
}

// ---------------------------------------------------------------------------
// bf16-split GEMM v2: 4 warps x (64x64) warp tiles, CTA 128x128, BK=16,
// 3-stage cp.async. 96 MMAs per 16 ldsm (density 6.0 vs 4.0).
// MODE 0: scatter Q(scaled)/K/V hi+lo head-major    MODE 1: fp32 C + bias
// ---------------------------------------------------------------------------
template<int MODE>
__global__ __launch_bounds__(128, 2) void gemm_bf16_kernel(
    const __nv_bfloat16* __restrict__ Ah, const __nv_bfloat16* __restrict__ Al,
    const __nv_bfloat16* __restrict__ Bh, const __nv_bfloat16* __restrict__ Bl,
    const float* __restrict__ bias, float* __restrict__ C, int Nfull)
{
    __shared__ __align__(16) uint8_t sm[3 * 16384];   // 3 stages x (Ah,Al,Bh,Bl @4KB)

    const int tid  = threadIdx.x;
    const int lane = tid & 31;
    const int wid  = tid >> 5;          // 0..3
    const int wm   = wid >> 1;          // 0..1 (m dim, 64 rows)
    const int wn   = wid & 1;           // 0..1 (n dim, 64 cols)
    const int m0   = blockIdx.y * 128;
    const int n0   = blockIdx.x * 128;
    const uint32_t uSm = smem_u32(sm);

    // loader: 128 threads, each owns one tile row (both 16B chunks) per tile
    const uint32_t lo0 = tile_off(tid, 0);
    const uint32_t lo1 = tile_off(tid, 1);

    auto issue = [&](int buf, int it) {
        const int k0 = it * 16;
        const uint32_t s = uSm + buf * 16384;
        const __nv_bfloat16* a_h = Ah + (size_t)(m0 + tid) * GEMM_K + k0;
        const __nv_bfloat16* a_l = Al + (size_t)(m0 + tid) * GEMM_K + k0;
        const __nv_bfloat16* b_h = Bh + (size_t)(n0 + tid) * GEMM_K + k0;
        const __nv_bfloat16* b_l = Bl + (size_t)(n0 + tid) * GEMM_K + k0;
        cp16(s + lo0,          a_h);     cp16(s + lo1,          a_h + 8);
        cp16(s + 4096 + lo0,   a_l);     cp16(s + 4096 + lo1,   a_l + 8);
        cp16(s + 8192 + lo0,   b_h);     cp16(s + 8192 + lo1,   b_h + 8);
        cp16(s + 12288 + lo0,  b_l);     cp16(s + 12288 + lo1,  b_l + 8);
    };

    float acc[4][8][4];
#pragma unroll
    for (int t = 0; t < 4; t++)
#pragma unroll
        for (int u = 0; u < 8; u++)
#pragma unroll
            for (int e = 0; e < 4; e++) acc[t][u][e] = 0.f;

    issue(0, 0); CP_COMMIT();
    issue(1, 1); CP_COMMIT();

    const int arow = wm * 64 + (lane & 15);
    const int achk = lane >> 4;
    const int brow = wn * 64 + (lane & 7) + ((lane >> 4) << 3);
    const int bchk = (lane >> 3) & 1;

    for (int it = 0; it < GEMM_K / 16; ++it) {
        if (it >= GEMM_K / 16 - 2) { CP_WAIT0(); } else { CP_WAIT1(); }
        __syncthreads();
        if (it + 2 < GEMM_K / 16) { issue((it + 2) % 3, it + 2); CP_COMMIT(); }

        const uint32_t s  = uSm + (it % 3) * 16384;
        const uint32_t bAh = s, bAl = s + 4096, bBh = s + 8192, bBl = s + 12288;

        uint32_t aH[4][4], aL[4][4], bH[16], bL[16];
#pragma unroll
        for (int t = 0; t < 4; t++) {
            const uint32_t off = tile_off(arow + t * 16, achk);
            ldsm4(bAh + off, aH[t]);
            ldsm4(bAl + off, aL[t]);
        }
#pragma unroll
        for (int nb = 0; nb < 4; nb++) {
            const uint32_t off = tile_off(brow + nb * 16, bchk);
            ldsm4(bBh + off, &bH[nb * 4]);
            ldsm4(bBl + off, &bL[nb * 4]);
        }
        // 96 MMAs, 32 independent accumulators per term
#pragma unroll
        for (int t = 0; t < 4; t++)
#pragma unroll
            for (int u = 0; u < 8; u++)
                mma_bf16(acc[t][u], aH[t], &bH[(u >> 1) * 4 + (u & 1) * 2]);
#pragma unroll
        for (int t = 0; t < 4; t++)
#pragma unroll
            for (int u = 0; u < 8; u++)
                mma_bf16(acc[t][u], aH[t], &bL[(u >> 1) * 4 + (u & 1) * 2]);
#pragma unroll
        for (int t = 0; t < 4; t++)
#pragma unroll
            for (int u = 0; u < 8; u++)
                mma_bf16(acc[t][u], aL[t], &bH[(u >> 1) * 4 + (u & 1) * 2]);
        __syncthreads();
    }

    // ---- epilogue ----------------------------------------------------------
    const int mwarp = m0 + wm * 64;
    const int nwarp = n0 + wn * 64;
    const int g = lane >> 2, q = lane & 3;
#pragma unroll
    for (int u = 0; u < 8; u++) {
        const int n = nwarp + u * 8 + 2 * q;
        const float2 bv = *(const float2*)(bias + n);
#pragma unroll
        for (int t = 0; t < 4; t++) {
            const int m = mwarp + t * 16 + g;
            float2 v0 = make_float2(acc[t][u][0] + bv.x, acc[t][u][1] + bv.y);
            float2 v1 = make_float2(acc[t][u][2] + bv.x, acc[t][u][3] + bv.y);
            if (MODE == 1) {
                *(float2*)(C + (size_t)m * Nfull + n)       = v0;
                *(float2*)(C + (size_t)(m + 8) * Nfull + n) = v1;
            } else {
                const int which = n >> 10;
                const int e = n & 1023;
                const int h = e >> 6;
                const int d = e & 63;
                if (which == 0) { v0.x *= ATTN_SCALE; v0.y *= ATTN_SCALE;
                                  v1.x *= ATTN_SCALE; v1.y *= ATTN_SCALE; }
                __nv_bfloat16* dh = (which == 0) ? g_Qh : (which == 1) ? g_Kh : g_Vh;
                __nv_bfloat16* dl = (which == 0) ? g_Ql : (which == 1) ? g_Kl : g_Vl;
                const int b  = m >> 11;
                const size_t base = (((size_t)(b * NHEADS + h)) * NSEQ) * HDIM + d;
                const size_t o0 = base + (size_t)(m & 2047) * HDIM;
                const size_t o1 = base + (size_t)((m + 8) & 2047) * HDIM;
                *(uint32_t*)(dh + o0) = hipack(v0.x, v0.y);
                *(uint32_t*)(dl + o0) = lopack(v0.x, v0.y);
                *(uint32_t*)(dh + o1) = hipack(v1.x, v1.y);
                *(uint32_t*)(dl + o1) = lopack(v1.x, v1.y);
            }
        }
    }
}

// ---------------------------------------------------------------------------
// Flash attention v3.1 (unchanged): pure bf16, cp.async 2-stage KV,
// Q smem-resident, term-major MMA ordering.
// ---------------------------------------------------------------------------
#define FLASH_SMEM (32768 + 2*32768)   // Q(hi+lo 32KB) + 2 KV stages (32KB each)

__global__ __launch_bounds__(256, 2) void flash_mma_v3()
{
    extern __shared__ __align__(16) uint8_t sb[];
    const uint32_t uQh = smem_u32(sb);
    const uint32_t uQl = uQh + 16384;

    const int tid  = threadIdx.x;
    const int lane = tid & 31;
    const int wid  = tid >> 5;
    const int mt   = blockIdx.x;       // q tile (0..15)
    const int bh   = blockIdx.y;       // 0..31

    const size_t kvbase = (size_t)bh * NSEQ * HDIM;
    const __nv_bfloat16* Qhg = g_Qh + kvbase + (size_t)mt * 128 * HDIM;
    const __nv_bfloat16* Qlg = g_Ql + kvbase + (size_t)mt * 128 * HDIM;

    // Q load: 128 rows x 8 chunks x (hi,lo)
    {
        const int r = tid >> 1;                 // 0..127
        const int cb = (tid & 1) * 4;           // chunk base 0 or 4
#pragma unroll
        for (int c = 0; c < 4; c++) {
            cp16(uQh + swz128(r, cb + c), Qhg + (size_t)r * HDIM + (cb + c) * 8);
            cp16(uQl + swz128(r, cb + c), Qlg + (size_t)r * HDIM + (cb + c) * 8);
        }
    }

    auto issue_kv = [&](int t, int buf) {
        const uint32_t base = uQh + 32768 + buf * 32768;
        const __nv_bfloat16* Ks_h = g_Kh + kvbase + (size_t)t * 64 * HDIM;
        const __nv_bfloat16* Ks_l = g_Kl + kvbase + (size_t)t * 64 * HDIM;
        const __nv_bfloat16* Vs_h = g_Vh + kvbase + (size_t)t * 64 * HDIM;
        const __nv_bfloat16* Vs_l = g_Vl + kvbase + (size_t)t * 64 * HDIM;
#pragma unroll
        for (int i = 0; i < 2; i++) {
            const int id = tid + i * 256;       // 0..511
            const int r = id >> 3, c = id & 7;
            const uint32_t off = swz128(r, c);
            const size_t src = (size_t)r * HDIM + c * 8;
            cp16(base + off,          Ks_h + src);
            cp16(base + 8192 + off,   Ks_l + src);
            cp16(base + 16384 + off,  Vs_h + src);
            cp16(base + 24576 + off,  Vs_l + src);
        }
    };

    issue_kv(0, 0);
    CP_COMMIT();

    float of[8][4];
#pragma unroll
    for (int u = 0; u < 8; u++)
#pragma unroll
        for (int e = 0; e < 4; e++) of[u][e] = 0.f;
    float m0 = -1e30f, m1 = -1e30f, l0 = 0.f, l1 = 0.f;

    const int qrow = wid * 16 + (lane & 15);
    const int qsel = lane >> 4;
    const int brow = (lane & 7) + ((lane >> 4) << 3);
    const int bsel = (lane >> 3) & 1;
    const int vrow_l = lane & 15;
    const int vsel   = lane >> 4;

    for (int t = 0; t < NSEQ / 64; t++) {
        CP_WAIT0();
        __syncthreads();
        if (t + 1 < NSEQ / 64) { issue_kv(t + 1, (t + 1) & 1); CP_COMMIT(); }

        const uint32_t kvb = uQh + 32768 + (t & 1) * 32768;
        const uint32_t uKh = kvb, uKl = kvb + 8192;
        const uint32_t uVh = kvb + 16384, uVl = kvb + 24576;

        // ---- S = Q @ K^T (3-term, term-major) -----------------------------
        float sf[8][4];
#pragma unroll
        for (int u = 0; u < 8; u++)
#pragma unroll
            for (int e = 0; e < 4; e++) sf[u][e] = 0.f;

#pragma unroll
        for (int kc = 0; kc < 4; kc++) {
            uint32_t qh[4], ql[4];
            ldsm4(uQh + swz128(qrow, 2 * kc + qsel), qh);
            ldsm4(uQl + swz128(qrow, 2 * kc + qsel), ql);
            uint32_t bb[16];
#pragma unroll
            for (int nb = 0; nb < 4; nb++)
                ldsm4(uKh + swz128(nb * 16 + brow, 2 * kc + bsel), &bb[nb * 4]);
#pragma unroll
            for (int u = 0; u < 8; u++)
                mma_bf16(sf[u], qh, &bb[(u >> 1) * 4 + (u & 1) * 2]);
#pragma unroll
            for (int u = 0; u < 8; u++)
                mma_bf16(sf[u], ql, &bb[(u >> 1) * 4 + (u & 1) * 2]);
#pragma unroll
            for (int nb = 0; nb < 4; nb++)
                ldsm4(uKl + swz128(nb * 16 + brow, 2 * kc + bsel), &bb[nb * 4]);
#pragma unroll
            for (int u = 0; u < 8; u++)
                mma_bf16(sf[u], qh, &bb[(u >> 1) * 4 + (u & 1) * 2]);
        }

        // ---- online softmax ----------------------------------------------
        {
            float mx0 = -1e30f, mx1 = -1e30f;
#pragma unroll
            for (int u = 0; u < 8; u++) {
                mx0 = fmaxf(mx0, fmaxf(sf[u][0], sf[u][1]));
                mx1 = fmaxf(mx1, fmaxf(sf[u][2], sf[u][3]));
            }
            mx0 = fmaxf(mx0, __shfl_xor_sync(0xffffffffu, mx0, 1));
            mx0 = fmaxf(mx0, __shfl_xor_sync(0xffffffffu, mx0, 2));
            mx1 = fmaxf(mx1, __shfl_xor_sync(0xffffffffu, mx1, 1));
            mx1 = fmaxf(mx1, __shfl_xor_sync(0xffffffffu, mx1, 2));

            float mn0 = fmaxf(m0, mx0), mn1 = fmaxf(m1, mx1);
            float c0 = __expf(m0 - mn0), c1 = __expf(m1 - mn1);
            m0 = mn0; m1 = mn1;
            float s0 = 0.f, s1 = 0.f;
#pragma unroll
            for (int u = 0; u < 8; u++) {
                float p0 = __expf(sf[u][0] - mn0);
                float p1 = __expf(sf[u][1] - mn0);
                float p2 = __expf(sf[u][2] - mn1);
                float p3 = __expf(sf[u][3] - mn1);
                s0 += p0 + p1; s1 += p2 + p3;
                sf[u][0] = p0; sf[u][1] = p1; sf[u][2] = p2; sf[u][3] = p3;
            }
            s0 += __shfl_xor_sync(0xffffffffu, s0, 1);
            s0 += __shfl_xor_sync(0xffffffffu, s0, 2);
            s1 += __shfl_xor_sync(0xffffffffu, s1, 1);
            s1 += __shfl_xor_sync(0xffffffffu, s1, 2);
            l0 = l0 * c0 + s0; l1 = l1 * c1 + s1;
#pragma unroll
            for (int u = 0; u < 8; u++) {
                of[u][0] *= c0; of[u][1] *= c0;
                of[u][2] *= c1; of[u][3] *= c1;
            }
        }

        // ---- P frags (register hi/lo) -------------------------------------
        uint32_t pH[4][4], pL[4][4];
#pragma unroll
        for (int kc = 0; kc < 4; kc++) {
            pH[kc][0] = hipack(sf[2*kc][0],   sf[2*kc][1]);
            pH[kc][1] = hipack(sf[2*kc][2],   sf[2*kc][3]);
            pH[kc][2] = hipack(sf[2*kc+1][0], sf[2*kc+1][1]);
            pH[kc][3] = hipack(sf[2*kc+1][2], sf[2*kc+1][3]);
            pL[kc][0] = lopack(sf[2*kc][0],   sf[2*kc][1]);
            pL[kc][1] = lopack(sf[2*kc][2],   sf[2*kc][3]);
            pL[kc][2] = lopack(sf[2*kc+1][0], sf[2*kc+1][1]);
            pL[kc][3] = lopack(sf[2*kc+1][2], sf[2*kc+1][3]);
        }

        // ---- O += P @ V (3-term, term-major; V via ldmatrix.trans) --------
#pragma unroll
        for (int kc = 0; kc < 4; kc++) {
            uint32_t vv[16];
            const int row = 16 * kc + vrow_l;
#pragma unroll
            for (int vp = 0; vp < 4; vp++)
                ldsm4t(uVh + swz128(row, 2 * vp + vsel), &vv[vp * 4]);
#pragma unroll
            for (int u = 0; u < 8; u++)
                mma_bf16(of[u], pH[kc], &vv[(u >> 1) * 4 + (u & 1) * 2]);
#pragma unroll
            for (int u = 0; u < 8; u++)
                mma_bf16(of[u], pL[kc], &vv[(u >> 1) * 4 + (u & 1) * 2]);
#pragma unroll
            for (int vp = 0; vp < 4; vp++)
                ldsm4t(uVl + swz128(row, 2 * vp + vsel), &vv[vp * 4]);
#pragma unroll
            for (int u = 0; u < 8; u++)
                mma_bf16(of[u], pH[kc], &vv[(u >> 1) * 4 + (u & 1) * 2]);
        }
    }

    // ---- epilogue: normalize, write AO as bf16 hi/lo [B*N, E] --------------
    const float inv0 = __fdividef(1.f, l0);
    const float inv1 = __fdividef(1.f, l1);
    const int b = bh >> 4, h = bh & 15;
    const int g = lane >> 2, q = lane & 3;
    const int nrow = mt * 128 + wid * 16 + g;
    const size_t r0 = ((size_t)(b * NSEQ + nrow)) * EMBED + h * HDIM;
    const size_t r1 = r0 + (size_t)8 * EMBED;
#pragma unroll
    for (int u = 0; u < 8; u++) {
        const int col = 8 * u + 2 * q;
        float x0 = of[u][0] * inv0, y0 = of[u][1] * inv0;
        float x1 = of[u][2] * inv1, y1 = of[u][3] * inv1;
        *(uint32_t*)(g_AOh + r0 + col) = hipack(x0, y0);
        *(uint32_t*)(g_AOl + r0 + col) = lopack(x0, y0);
        *(uint32_t*)(g_AOh + r1 + col) = hipack(x1, y1);
        *(uint32_t*)(g_AOl + r1 + col) = lopack(x1, y1);
    }
}

// ---------------------------------------------------------------------------
extern "C" void kernel_launch(void* const* d_in, const int* in_sizes, int n_in,
                              void* d_out, int out_size)
{
    const float* x     = (const float*)d_in[0];
    const float* W_qkv = (const float*)d_in[1];
    const float* b_qkv = (const float*)d_in[2];
    const float* W_out = (const float*)d_in[3];
    const float* b_out = (const float*)d_in[4];
    float* out = (float*)d_out;

    __nv_bfloat16 *xh, *xl, *wqh, *wql, *woh, *wol, *aoh, *aol;
    cudaGetSymbolAddress((void**)&xh,  g_Xh);
    cudaGetSymbolAddress((void**)&xl,  g_Xl);
    cudaGetSymbolAddress((void**)&wqh, g_Wqh);
    cudaGetSymbolAddress((void**)&wql, g_Wql);
    cudaGetSymbolAddress((void**)&woh, g_Woh);
    cudaGetSymbolAddress((void**)&wol, g_Wol);
    cudaGetSymbolAddress((void**)&aoh, g_AOh);
    cudaGetSymbolAddress((void**)&aol, g_AOl);

    cudaFuncSetAttribute(flash_mma_v3,
                         cudaFuncAttributeMaxDynamicSharedMemorySize, FLASH_SMEM);

    // 0) one-time conversions
    convert_hl_kernel<<<(MTOT * EMBED / 4) / 256, 256>>>(x, xh, xl);
    transpose_hl_kernel<<<dim3(3*EMBED/32, EMBED/32), dim3(32, 8)>>>(W_qkv, wqh, wql, EMBED, 3*EMBED);
    transpose_hl_kernel<<<dim3(EMBED/32,   EMBED/32), dim3(32, 8)>>>(W_out, woh, wol, EMBED, EMBED);

    // 1) QKV projection -> Q(scaled)/K/V bf16 hi/lo head-major
    gemm_bf16_kernel<0><<<dim3(3*EMBED/128, MTOT/128), 128>>>(
        xh, xl, wqh, wql, b_qkv, nullptr, 3*EMBED);

    // 2) flash attention -> AO bf16 hi/lo
    flash_mma_v3<<<dim3(NSEQ/128, NB*NHEADS), 256, FLASH_SMEM>>>();

    // 3) output projection -> d_out (fp32)
    gemm_bf16_kernel<1><<<dim3(EMBED/128, MTOT/128), 128>>>(
        aoh, aol, woh, wol, b_out, out, EMBED);
}

// round 9
// speedup vs baseline: 1.0890x; 1.0890x over previous
#include <cuda_runtime.h>
#include <cuda_bf16.h>
#include <cstdint>
#include <math.h>

#define EMBED  1024
#define NHEADS 16
#define HDIM   64
#define NB     2
#define NSEQ   2048
#define MTOT   (NB*NSEQ)          // 4096
#define GEMM_K 1024
#define ATTN_SCALE 0.125f

// ---------------- scratch (__device__ globals) ------------------------------
__device__ __nv_bfloat16 g_Xh[MTOT*EMBED],      g_Xl[MTOT*EMBED];
__device__ __nv_bfloat16 g_Wqh[3*EMBED*EMBED],  g_Wql[3*EMBED*EMBED];
__device__ __nv_bfloat16 g_Woh[EMBED*EMBED],    g_Wol[EMBED*EMBED];
__device__ __nv_bfloat16 g_Qh[NB*NHEADS*NSEQ*HDIM], g_Ql[NB*NHEADS*NSEQ*HDIM];
__device__ __nv_bfloat16 g_Kh[NB*NHEADS*NSEQ*HDIM], g_Kl[NB*NHEADS*NSEQ*HDIM];
__device__ __nv_bfloat16 g_Vh[NB*NHEADS*NSEQ*HDIM], g_Vl[NB*NHEADS*NSEQ*HDIM];
__device__ __nv_bfloat16 g_AOh[MTOT*EMBED],     g_AOl[MTOT*EMBED];

// ---------------- helpers ---------------------------------------------------
__device__ __forceinline__ uint32_t smem_u32(const void* p) {
    uint32_t a;
    asm("{ .reg .u64 t; cvta.to.shared.u64 t, %1; cvt.u32.u64 %0, t; }"
        : "=r"(a) : "l"(p));
    return a;
}
__device__ __forceinline__ void ldsm4(uint32_t addr, uint32_t* r) {
    asm volatile("ldmatrix.sync.aligned.m8n8.x4.shared.b16 {%0,%1,%2,%3}, [%4];"
        : "=r"(r[0]), "=r"(r[1]), "=r"(r[2]), "=r"(r[3]) : "r"(addr));
}
__device__ __forceinline__ void ldsm4t(uint32_t addr, uint32_t* r) {
    asm volatile("ldmatrix.sync.aligned.m8n8.x4.trans.shared.b16 {%0,%1,%2,%3}, [%4];"
        : "=r"(r[0]), "=r"(r[1]), "=r"(r[2]), "=r"(r[3]) : "r"(addr));
}
__device__ __forceinline__ void mma_bf16(float* d, const uint32_t* a, const uint32_t* b) {
    asm volatile(
        "mma.sync.aligned.m16n8k16.row.col.f32.bf16.bf16.f32 "
        "{%0,%1,%2,%3},{%4,%5,%6,%7},{%8,%9},{%0,%1,%2,%3};"
        : "+f"(d[0]), "+f"(d[1]), "+f"(d[2]), "+f"(d[3])
        : "r"(a[0]), "r"(a[1]), "r"(a[2]), "r"(a[3]), "r"(b[0]), "r"(b[1]));
}
__device__ __forceinline__ void cp16(uint32_t s, const void* g) {
    asm volatile("cp.async.cg.shared.global [%0], [%1], 16;" :: "r"(s), "l"(g));
}
#define CP_COMMIT() asm volatile("cp.async.commit_group;" ::: "memory")
#define CP_WAIT0()  asm volatile("cp.async.wait_group 0;" ::: "memory")
#define CP_WAIT2()  asm volatile("cp.async.wait_group 2;" ::: "memory")

__device__ __forceinline__ uint32_t bits_bf162(__nv_bfloat162 h) {
    return *reinterpret_cast<uint32_t*>(&h);
}
__device__ __forceinline__ uint32_t hipack(float x, float y) {
    return (__float_as_uint(x) >> 16) | (__float_as_uint(y) & 0xffff0000u);
}
__device__ __forceinline__ uint32_t lopack(float x, float y) {
    float lx = x - __uint_as_float(__float_as_uint(x) & 0xffff0000u);
    float ly = y - __uint_as_float(__float_as_uint(y) & 0xffff0000u);
    return bits_bf162(__floats2bfloat162_rn(lx, ly));
}
__device__ __forceinline__ void cvt_hl(float4 v, uint2& h, uint2& l) {
    h.x = hipack(v.x, v.y); h.y = hipack(v.z, v.w);
    l.x = lopack(v.x, v.y); l.y = lopack(v.z, v.w);
}
// 128B-row swizzle (flash tiles): 16B chunk XOR row%8
__device__ __forceinline__ uint32_t swz128(int row, int chunk) {
    return (uint32_t)(row * 128 + ((chunk ^ (row & 7)) << 4));
}
// 32B-row GEMM tile swizzle: chunk(0/1) XOR (row>>2)&1
__device__ __forceinline__ uint32_t tile_off(int r, int chunk) {
    return (uint32_t)(r * 32 + ((chunk ^ ((r >> 2) & 1)) << 4));
}

// ---------------------------------------------------------------------------
// Pre-kernels: one-time conversions
// ---------------------------------------------------------------------------
__global__ void convert_hl_kernel(const float* __restrict__ S,
                                  __nv_bfloat16* __restrict__ Dh,
                                  __nv_bfloat16* __restrict__ Dl)
{
    int i = blockIdx.x * blockDim.x + threadIdx.x;   // float4 index
    float4 v = ((const float4*)S)[i];
    uint2 h, l; cvt_hl(v, h, l);
    ((uint2*)Dh)[i] = h;
    ((uint2*)Dl)[i] = l;
}

// src[K][N] f32 -> dst[N][K] bf16 hi/lo
__global__ void transpose_hl_kernel(const float* __restrict__ S,
                                    __nv_bfloat16* __restrict__ Dh,
                                    __nv_bfloat16* __restrict__ Dl,
                                    int K, int N)
{
    __shared__ float t[32][33];
    int bx = blockIdx.x * 32;   // N dim
    int by = blockIdx.y * 32;   // K dim
    int tx = threadIdx.x, ty = threadIdx.y;
#pragma unroll
    for (int j = 0; j < 32; j += 8)
        t[ty + j][tx] = S[(size_t)(by + ty + j) * N + bx + tx];
    __syncthreads();
#pragma unroll
    for (int j = 0; j < 32; j += 8) {
        float v = t[tx][ty + j];
        size_t idx = (size_t)(bx + ty + j) * K + by + tx;
        uint32_t u = __float_as_uint(v);
        ((uint16_t*)Dh)[idx] = (uint16_t)(u >> 16);
        float lr = v - __uint_as_float(u & 0xffff0000u);
        __nv_bfloat16 lb = __float2bfloat16(lr);
        ((uint16_t*)Dl)[idx] = *reinterpret_cast<uint16_t*>(&lb);
    }
}

// ---------------------------------------------------------------------------
// bf16-split GEMM v3: round-7 shape (8 warps, 64x32 warp tiles) with a
// 4-stage cp.async pipeline (64KB dynamic smem) and ONE sync per K-iter.
// MODE 0: scatter Q(scaled)/K/V hi+lo head-major    MODE 1: fp32 C + bias
// ---------------------------------------------------------------------------
#define GEMM_SMEM (4 * 16384)
#define NITER     (GEMM_K / 16)

template<int MODE>
__global__ __launch_bounds__(256, 2) void gemm_bf16_kernel(
    const __nv_bfloat16* __restrict__ Ah, const __nv_bfloat16* __restrict__ Al,
    const __nv_bfloat16* __restrict__ Bh, const __nv_bfloat16* __restrict__ Bl,
    const float* __restrict__ bias, float* __restrict__ C, int Nfull)
{
    extern __shared__ __align__(16) uint8_t smg[];   // 4 stages x (Ah,Al,Bh,Bl @4KB)

    const int tid  = threadIdx.x;
    const int lane = tid & 31;
    const int wid  = tid >> 5;
    const int wm   = wid >> 2;
    const int wn   = wid & 3;
    const int m0   = blockIdx.y * 128;
    const int n0   = blockIdx.x * 128;
    const uint32_t uSm = smem_u32(smg);

    const int lr = tid >> 1, lc = tid & 1;
    const uint32_t loff = tile_off(lr, lc);

    auto issue = [&](int buf, int it) {
        const int k0 = it * 16;
        const uint32_t s = uSm + buf * 16384;
        cp16(s + loff,         Ah + (size_t)(m0 + lr) * GEMM_K + k0 + lc * 8);
        cp16(s + 4096 + loff,  Al + (size_t)(m0 + lr) * GEMM_K + k0 + lc * 8);
        cp16(s + 8192 + loff,  Bh + (size_t)(n0 + lr) * GEMM_K + k0 + lc * 8);
        cp16(s + 12288 + loff, Bl + (size_t)(n0 + lr) * GEMM_K + k0 + lc * 8);
    };

    float acc[4][4][4];
#pragma unroll
    for (int t = 0; t < 4; t++)
#pragma unroll
        for (int u = 0; u < 4; u++)
#pragma unroll
            for (int e = 0; e < 4; e++) acc[t][u][e] = 0.f;

    issue(0, 0); CP_COMMIT();
    issue(1, 1); CP_COMMIT();
    issue(2, 2); CP_COMMIT();

    const int arow = wm * 64 + (lane & 15);
    const int achk = lane >> 4;
    const int brow_base = wn * 32 + (lane & 7) + ((lane >> 4) << 3);
    const int bchk = (lane >> 3) & 1;

    for (int it = 0; it < NITER; ++it) {
        if (it >= NITER - 3) { CP_WAIT0(); } else { CP_WAIT2(); }
        __syncthreads();                       // the ONLY barrier per iter
        if (it + 3 < NITER) { issue((it + 3) & 3, it + 3); CP_COMMIT(); }

        const uint32_t s  = uSm + (it & 3) * 16384;
        const uint32_t bAh = s, bAl = s + 4096, bBh = s + 8192, bBl = s + 12288;

        uint32_t aH[4][4], aL[4][4], bH[8], bL[8];
#pragma unroll
        for (int t = 0; t < 4; t++) {
            const uint32_t off = tile_off(arow + t * 16, achk);
            ldsm4(bAh + off, aH[t]);
            ldsm4(bAl + off, aL[t]);
        }
#pragma unroll
        for (int p = 0; p < 2; p++) {
            const uint32_t off = tile_off(brow_base + p * 16, bchk);
            ldsm4(bBh + off, &bH[p * 4]);
            ldsm4(bBl + off, &bL[p * 4]);
        }
#pragma unroll
        for (int t = 0; t < 4; t++)
#pragma unroll
            for (int u = 0; u < 4; u++)
                mma_bf16(acc[t][u], aH[t], &bH[(u >> 1) * 4 + (u & 1) * 2]);
#pragma unroll
        for (int t = 0; t < 4; t++)
#pragma unroll
            for (int u = 0; u < 4; u++)
                mma_bf16(acc[t][u], aH[t], &bL[(u >> 1) * 4 + (u & 1) * 2]);
#pragma unroll
        for (int t = 0; t < 4; t++)
#pragma unroll
            for (int u = 0; u < 4; u++)
                mma_bf16(acc[t][u], aL[t], &bH[(u >> 1) * 4 + (u & 1) * 2]);
        // no trailing sync: top-of-loop barrier orders stage reuse
    }

    // ---- epilogue ----------------------------------------------------------
    const int mwarp = m0 + wm * 64;
    const int nwarp = n0 + wn * 32;
    const int g = lane >> 2, q = lane & 3;
#pragma unroll
    for (int u = 0; u < 4; u++) {
        const int n = nwarp + u * 8 + 2 * q;
        const float2 bv = *(const float2*)(bias + n);
#pragma unroll
        for (int t = 0; t < 4; t++) {
            const int m = mwarp + t * 16 + g;
            float2 v0 = make_float2(acc[t][u][0] + bv.x, acc[t][u][1] + bv.y);
            float2 v1 = make_float2(acc[t][u][2] + bv.x, acc[t][u][3] + bv.y);
            if (MODE == 1) {
                *(float2*)(C + (size_t)m * Nfull + n)       = v0;
                *(float2*)(C + (size_t)(m + 8) * Nfull + n) = v1;
            } else {
                const int which = n >> 10;
                const int e = n & 1023;
                const int h = e >> 6;
                const int d = e & 63;
                if (which == 0) { v0.x *= ATTN_SCALE; v0.y *= ATTN_SCALE;
                                  v1.x *= ATTN_SCALE; v1.y *= ATTN_SCALE; }
                __nv_bfloat16* dh = (which == 0) ? g_Qh : (which == 1) ? g_Kh : g_Vh;
                __nv_bfloat16* dl = (which == 0) ? g_Ql : (which == 1) ? g_Kl : g_Vl;
                const int b  = m >> 11;
                const size_t base = (((size_t)(b * NHEADS + h)) * NSEQ) * HDIM + d;
                const size_t o0 = base + (size_t)(m & 2047) * HDIM;
                const size_t o1 = base + (size_t)((m + 8) & 2047) * HDIM;
                *(uint32_t*)(dh + o0) = hipack(v0.x, v0.y);
                *(uint32_t*)(dl + o0) = lopack(v0.x, v0.y);
                *(uint32_t*)(dh + o1) = hipack(v1.x, v1.y);
                *(uint32_t*)(dl + o1) = lopack(v1.x, v1.y);
            }
        }
    }
}

// ---------------------------------------------------------------------------
// Flash attention v3.1 (unchanged from round 7)
// ---------------------------------------------------------------------------
#define FLASH_SMEM (32768 + 2*32768)   // Q(hi+lo 32KB) + 2 KV stages (32KB each)

__global__ __launch_bounds__(256, 2) void flash_mma_v3()
{
    extern __shared__ __align__(16) uint8_t sb[];
    const uint32_t uQh = smem_u32(sb);
    const uint32_t uQl = uQh + 16384;

    const int tid  = threadIdx.x;
    const int lane = tid & 31;
    const int wid  = tid >> 5;
    const int mt   = blockIdx.x;       // q tile (0..15)
    const int bh   = blockIdx.y;       // 0..31

    const size_t kvbase = (size_t)bh * NSEQ * HDIM;
    const __nv_bfloat16* Qhg = g_Qh + kvbase + (size_t)mt * 128 * HDIM;
    const __nv_bfloat16* Qlg = g_Ql + kvbase + (size_t)mt * 128 * HDIM;

    {
        const int r = tid >> 1;
        const int cb = (tid & 1) * 4;
#pragma unroll
        for (int c = 0; c < 4; c++) {
            cp16(uQh + swz128(r, cb + c), Qhg + (size_t)r * HDIM + (cb + c) * 8);
            cp16(uQl + swz128(r, cb + c), Qlg + (size_t)r * HDIM + (cb + c) * 8);
        }
    }

    auto issue_kv = [&](int t, int buf) {
        const uint32_t base = uQh + 32768 + buf * 32768;
        const __nv_bfloat16* Ks_h = g_Kh + kvbase + (size_t)t * 64 * HDIM;
        const __nv_bfloat16* Ks_l = g_Kl + kvbase + (size_t)t * 64 * HDIM;
        const __nv_bfloat16* Vs_h = g_Vh + kvbase + (size_t)t * 64 * HDIM;
        const __nv_bfloat16* Vs_l = g_Vl + kvbase + (size_t)t * 64 * HDIM;
#pragma unroll
        for (int i = 0; i < 2; i++) {
            const int id = tid + i * 256;
            const int r = id >> 3, c = id & 7;
            const uint32_t off = swz128(r, c);
            const size_t src = (size_t)r * HDIM + c * 8;
            cp16(base + off,          Ks_h + src);
            cp16(base + 8192 + off,   Ks_l + src);
            cp16(base + 16384 + off,  Vs_h + src);
            cp16(base + 24576 + off,  Vs_l + src);
        }
    };

    issue_kv(0, 0);
    CP_COMMIT();

    float of[8][4];
#pragma unroll
    for (int u = 0; u < 8; u++)
#pragma unroll
        for (int e = 0; e < 4; e++) of[u][e] = 0.f;
    float m0 = -1e30f, m1 = -1e30f, l0 = 0.f, l1 = 0.f;

    const int qrow = wid * 16 + (lane & 15);
    const int qsel = lane >> 4;
    const int brow = (lane & 7) + ((lane >> 4) << 3);
    const int bsel = (lane >> 3) & 1;
    const int vrow_l = lane & 15;
    const int vsel   = lane >> 4;

    for (int t = 0; t < NSEQ / 64; t++) {
        CP_WAIT0();
        __syncthreads();
        if (t + 1 < NSEQ / 64) { issue_kv(t + 1, (t + 1) & 1); CP_COMMIT(); }

        const uint32_t kvb = uQh + 32768 + (t & 1) * 32768;
        const uint32_t uKh = kvb, uKl = kvb + 8192;
        const uint32_t uVh = kvb + 16384, uVl = kvb + 24576;

        float sf[8][4];
#pragma unroll
        for (int u = 0; u < 8; u++)
#pragma unroll
            for (int e = 0; e < 4; e++) sf[u][e] = 0.f;

#pragma unroll
        for (int kc = 0; kc < 4; kc++) {
            uint32_t qh[4], ql[4];
            ldsm4(uQh + swz128(qrow, 2 * kc + qsel), qh);
            ldsm4(uQl + swz128(qrow, 2 * kc + qsel), ql);
            uint32_t bb[16];
#pragma unroll
            for (int nb = 0; nb < 4; nb++)
                ldsm4(uKh + swz128(nb * 16 + brow, 2 * kc + bsel), &bb[nb * 4]);
#pragma unroll
            for (int u = 0; u < 8; u++)
                mma_bf16(sf[u], qh, &bb[(u >> 1) * 4 + (u & 1) * 2]);
#pragma unroll
            for (int u = 0; u < 8; u++)
                mma_bf16(sf[u], ql, &bb[(u >> 1) * 4 + (u & 1) * 2]);
#pragma unroll
            for (int nb = 0; nb < 4; nb++)
                ldsm4(uKl + swz128(nb * 16 + brow, 2 * kc + bsel), &bb[nb * 4]);
#pragma unroll
            for (int u = 0; u < 8; u++)
                mma_bf16(sf[u], qh, &bb[(u >> 1) * 4 + (u & 1) * 2]);
        }

        {
            float mx0 = -1e30f, mx1 = -1e30f;
#pragma unroll
            for (int u = 0; u < 8; u++) {
                mx0 = fmaxf(mx0, fmaxf(sf[u][0], sf[u][1]));
                mx1 = fmaxf(mx1, fmaxf(sf[u][2], sf[u][3]));
            }
            mx0 = fmaxf(mx0, __shfl_xor_sync(0xffffffffu, mx0, 1));
            mx0 = fmaxf(mx0, __shfl_xor_sync(0xffffffffu, mx0, 2));
            mx1 = fmaxf(mx1, __shfl_xor_sync(0xffffffffu, mx1, 1));
            mx1 = fmaxf(mx1, __shfl_xor_sync(0xffffffffu, mx1, 2));

            float mn0 = fmaxf(m0, mx0), mn1 = fmaxf(m1, mx1);
            float c0 = __expf(m0 - mn0), c1 = __expf(m1 - mn1);
            m0 = mn0; m1 = mn1;
            float s0 = 0.f, s1 = 0.f;
#pragma unroll
            for (int u = 0; u < 8; u++) {
                float p0 = __expf(sf[u][0] - mn0);
                float p1 = __expf(sf[u][1] - mn0);
                float p2 = __expf(sf[u][2] - mn1);
                float p3 = __expf(sf[u][3] - mn1);
                s0 += p0 + p1; s1 += p2 + p3;
                sf[u][0] = p0; sf[u][1] = p1; sf[u][2] = p2; sf[u][3] = p3;
            }
            s0 += __shfl_xor_sync(0xffffffffu, s0, 1);
            s0 += __shfl_xor_sync(0xffffffffu, s0, 2);
            s1 += __shfl_xor_sync(0xffffffffu, s1, 1);
            s1 += __shfl_xor_sync(0xffffffffu, s1, 2);
            l0 = l0 * c0 + s0; l1 = l1 * c1 + s1;
#pragma unroll
            for (int u = 0; u < 8; u++) {
                of[u][0] *= c0; of[u][1] *= c0;
                of[u][2] *= c1; of[u][3] *= c1;
            }
        }

        uint32_t pH[4][4], pL[4][4];
#pragma unroll
        for (int kc = 0; kc < 4; kc++) {
            pH[kc][0] = hipack(sf[2*kc][0],   sf[2*kc][1]);
            pH[kc][1] = hipack(sf[2*kc][2],   sf[2*kc][3]);
            pH[kc][2] = hipack(sf[2*kc+1][0], sf[2*kc+1][1]);
            pH[kc][3] = hipack(sf[2*kc+1][2], sf[2*kc+1][3]);
            pL[kc][0] = lopack(sf[2*kc][0],   sf[2*kc][1]);
            pL[kc][1] = lopack(sf[2*kc][2],   sf[2*kc][3]);
            pL[kc][2] = lopack(sf[2*kc+1][0], sf[2*kc+1][1]);
            pL[kc][3] = lopack(sf[2*kc+1][2], sf[2*kc+1][3]);
        }

#pragma unroll
        for (int kc = 0; kc < 4; kc++) {
            uint32_t vv[16];
            const int row = 16 * kc + vrow_l;
#pragma unroll
            for (int vp = 0; vp < 4; vp++)
                ldsm4t(uVh + swz128(row, 2 * vp + vsel), &vv[vp * 4]);
#pragma unroll
            for (int u = 0; u < 8; u++)
                mma_bf16(of[u], pH[kc], &vv[(u >> 1) * 4 + (u & 1) * 2]);
#pragma unroll
            for (int u = 0; u < 8; u++)
                mma_bf16(of[u], pL[kc], &vv[(u >> 1) * 4 + (u & 1) * 2]);
#pragma unroll
            for (int vp = 0; vp < 4; vp++)
                ldsm4t(uVl + swz128(row, 2 * vp + vsel), &vv[vp * 4]);
#pragma unroll
            for (int u = 0; u < 8; u++)
                mma_bf16(of[u], pH[kc], &vv[(u >> 1) * 4 + (u & 1) * 2]);
        }
    }

    const float inv0 = __fdividef(1.f, l0);
    const float inv1 = __fdividef(1.f, l1);
    const int b = bh >> 4, h = bh & 15;
    const int g = lane >> 2, q = lane & 3;
    const int nrow = mt * 128 + wid * 16 + g;
    const size_t r0 = ((size_t)(b * NSEQ + nrow)) * EMBED + h * HDIM;
    const size_t r1 = r0 + (size_t)8 * EMBED;
#pragma unroll
    for (int u = 0; u < 8; u++) {
        const int col = 8 * u + 2 * q;
        float x0 = of[u][0] * inv0, y0 = of[u][1] * inv0;
        float x1 = of[u][2] * inv1, y1 = of[u][3] * inv1;
        *(uint32_t*)(g_AOh + r0 + col) = hipack(x0, y0);
        *(uint32_t*)(g_AOl + r0 + col) = lopack(x0, y0);
        *(uint32_t*)(g_AOh + r1 + col) = hipack(x1, y1);
        *(uint32_t*)(g_AOl + r1 + col) = lopack(x1, y1);
    }
}

// ---------------------------------------------------------------------------
extern "C" void kernel_launch(void* const* d_in, const int* in_sizes, int n_in,
                              void* d_out, int out_size)
{
    const float* x     = (const float*)d_in[0];
    const float* W_qkv = (const float*)d_in[1];
    const float* b_qkv = (const float*)d_in[2];
    const float* W_out = (const float*)d_in[3];
    const float* b_out = (const float*)d_in[4];
    float* out = (float*)d_out;

    __nv_bfloat16 *xh, *xl, *wqh, *wql, *woh, *wol, *aoh, *aol;
    cudaGetSymbolAddress((void**)&xh,  g_Xh);
    cudaGetSymbolAddress((void**)&xl,  g_Xl);
    cudaGetSymbolAddress((void**)&wqh, g_Wqh);
    cudaGetSymbolAddress((void**)&wql, g_Wql);
    cudaGetSymbolAddress((void**)&woh, g_Woh);
    cudaGetSymbolAddress((void**)&wol, g_Wol);
    cudaGetSymbolAddress((void**)&aoh, g_AOh);
    cudaGetSymbolAddress((void**)&aol, g_AOl);

    cudaFuncSetAttribute(flash_mma_v3,
                         cudaFuncAttributeMaxDynamicSharedMemorySize, FLASH_SMEM);
    cudaFuncSetAttribute(gemm_bf16_kernel<0>,
                         cudaFuncAttributeMaxDynamicSharedMemorySize, GEMM_SMEM);
    cudaFuncSetAttribute(gemm_bf16_kernel<1>,
                         cudaFuncAttributeMaxDynamicSharedMemorySize, GEMM_SMEM);

    // 0) one-time conversions
    convert_hl_kernel<<<(MTOT * EMBED / 4) / 256, 256>>>(x, xh, xl);
    transpose_hl_kernel<<<dim3(3*EMBED/32, EMBED/32), dim3(32, 8)>>>(W_qkv, wqh, wql, EMBED, 3*EMBED);
    transpose_hl_kernel<<<dim3(EMBED/32,   EMBED/32), dim3(32, 8)>>>(W_out, woh, wol, EMBED, EMBED);

    // 1) QKV projection -> Q(scaled)/K/V bf16 hi/lo head-major
    gemm_bf16_kernel<0><<<dim3(3*EMBED/128, MTOT/128), 256, GEMM_SMEM>>>(
        xh, xl, wqh, wql, b_qkv, nullptr, 3*EMBED);

    // 2) flash attention -> AO bf16 hi/lo
    flash_mma_v3<<<dim3(NSEQ/128, NB*NHEADS), 256, FLASH_SMEM>>>();

    // 3) output projection -> d_out (fp32)
    gemm_bf16_kernel<1><<<dim3(EMBED/128, MTOT/128), 256, GEMM_SMEM>>>(
        aoh, aol, woh, wol, b_out, out, EMBED);
}

// round 11
// speedup vs baseline: 1.0895x; 1.0004x over previous
#include <cuda_runtime.h>
#include <cuda_bf16.h>
#include <cstdint>
#include <math.h>

#define EMBED  1024
#define NHEADS 16
#define HDIM   64
#define NB     2
#define NSEQ   2048
#define MTOT   (NB*NSEQ)          // 4096
#define GEMM_K 1024
#define ATTN_SCALE 0.125f

// ---------------- scratch (__device__ globals) ------------------------------
__device__ __nv_bfloat16 g_Xh[MTOT*EMBED],      g_Xl[MTOT*EMBED];
__device__ __nv_bfloat16 g_Wqh[3*EMBED*EMBED],  g_Wql[3*EMBED*EMBED];
__device__ __nv_bfloat16 g_Woh[EMBED*EMBED],    g_Wol[EMBED*EMBED];
__device__ __nv_bfloat16 g_Qh[NB*NHEADS*NSEQ*HDIM], g_Ql[NB*NHEADS*NSEQ*HDIM];
__device__ __nv_bfloat16 g_Kh[NB*NHEADS*NSEQ*HDIM], g_Kl[NB*NHEADS*NSEQ*HDIM];
__device__ __nv_bfloat16 g_Vh[NB*NHEADS*NSEQ*HDIM], g_Vl[NB*NHEADS*NSEQ*HDIM];
__device__ __nv_bfloat16 g_AOh[MTOT*EMBED],     g_AOl[MTOT*EMBED];

// ---------------- helpers ---------------------------------------------------
__device__ __forceinline__ uint32_t smem_u32(const void* p) {
    uint32_t a;
    asm("{ .reg .u64 t; cvta.to.shared.u64 t, %1; cvt.u32.u64 %0, t; }"
        : "=r"(a) : "l"(p));
    return a;
}
__device__ __forceinline__ void ldsm4(uint32_t addr, uint32_t* r) {
    asm volatile("ldmatrix.sync.aligned.m8n8.x4.shared.b16 {%0,%1,%2,%3}, [%4];"
        : "=r"(r[0]), "=r"(r[1]), "=r"(r[2]), "=r"(r[3]) : "r"(addr));
}
__device__ __forceinline__ void ldsm4t(uint32_t addr, uint32_t* r) {
    asm volatile("ldmatrix.sync.aligned.m8n8.x4.trans.shared.b16 {%0,%1,%2,%3}, [%4];"
        : "=r"(r[0]), "=r"(r[1]), "=r"(r[2]), "=r"(r[3]) : "r"(addr));
}
__device__ __forceinline__ void mma_bf16(float* d, const uint32_t* a, const uint32_t* b) {
    asm volatile(
        "mma.sync.aligned.m16n8k16.row.col.f32.bf16.bf16.f32 "
        "{%0,%1,%2,%3},{%4,%5,%6,%7},{%8,%9},{%0,%1,%2,%3};"
        : "+f"(d[0]), "+f"(d[1]), "+f"(d[2]), "+f"(d[3])
        : "r"(a[0]), "r"(a[1]), "r"(a[2]), "r"(a[3]), "r"(b[0]), "r"(b[1]));
}
__device__ __forceinline__ void cp16(uint32_t s, const void* g) {
    asm volatile("cp.async.cg.shared.global [%0], [%1], 16;" :: "r"(s), "l"(g));
}
#define CP_COMMIT() asm volatile("cp.async.commit_group;" ::: "memory")
#define CP_WAIT0()  asm volatile("cp.async.wait_group 0;" ::: "memory")
#define CP_WAIT1()  asm volatile("cp.async.wait_group 1;" ::: "memory")

__device__ __forceinline__ uint32_t bits_bf162(__nv_bfloat162 h) {
    return *reinterpret_cast<uint32_t*>(&h);
}
__device__ __forceinline__ uint32_t hipack(float x, float y) {
    return (__float_as_uint(x) >> 16) | (__float_as_uint(y) & 0xffff0000u);
}
__device__ __forceinline__ uint32_t lopack(float x, float y) {
    float lx = x - __uint_as_float(__float_as_uint(x) & 0xffff0000u);
    float ly = y - __uint_as_float(__float_as_uint(y) & 0xffff0000u);
    return bits_bf162(__floats2bfloat162_rn(lx, ly));
}
__device__ __forceinline__ void cvt_hl(float4 v, uint2& h, uint2& l) {
    h.x = hipack(v.x, v.y); h.y = hipack(v.z, v.w);
    l.x = lopack(v.x, v.y); l.y = lopack(v.z, v.w);
}
// 128B-row swizzle (flash tiles): 16B chunk XOR row%8
__device__ __forceinline__ uint32_t swz128(int row, int chunk) {
    return (uint32_t)(row * 128 + ((chunk ^ (row & 7)) << 4));
}
// 64B-row swizzle (GEMM BK=32 tiles): chunk(0..3) XOR (row>>1)&3
__device__ __forceinline__ uint32_t swz64(int row, int chunk) {
    return (uint32_t)(row * 64 + ((chunk ^ ((row >> 1) & 3)) << 4));
}

// ---------------------------------------------------------------------------
// Pre-kernels: one-time conversions
// ---------------------------------------------------------------------------
__global__ void convert_hl_kernel(const float* __restrict__ S,
                                  __nv_bfloat16* __restrict__ Dh,
                                  __nv_bfloat16* __restrict__ Dl)
{
    int i = blockIdx.x * blockDim.x + threadIdx.x;   // float4 index
    float4 v = ((const float4*)S)[i];
    uint2 h, l; cvt_hl(v, h, l);
    ((uint2*)Dh)[i] = h;
    ((uint2*)Dl)[i] = l;
}

// src[K][N] f32 -> dst[N][K] bf16 hi/lo
__global__ void transpose_hl_kernel(const float* __restrict__ S,
                                    __nv_bfloat16* __restrict__ Dh,
                                    __nv_bfloat16* __restrict__ Dl,
                                    int K, int N)
{
    __shared__ float t[32][33];
    int bx = blockIdx.x * 32;   // N dim
    int by = blockIdx.y * 32;   // K dim
    int tx = threadIdx.x, ty = threadIdx.y;
#pragma unroll
    for (int j = 0; j < 32; j += 8)
        t[ty + j][tx] = S[(size_t)(by + ty + j) * N + bx + tx];
    __syncthreads();
#pragma unroll
    for (int j = 0; j < 32; j += 8) {
        float v = t[tx][ty + j];
        size_t idx = (size_t)(bx + ty + j) * K + by + tx;
        uint32_t u = __float_as_uint(v);
        ((uint16_t*)Dh)[idx] = (uint16_t)(u >> 16);
        float lr = v - __uint_as_float(u & 0xffff0000u);
        __nv_bfloat16 lb = __float2bfloat16(lr);
        ((uint16_t*)Dl)[idx] = *reinterpret_cast<uint16_t*>(&lb);
    }
}

// ---------------------------------------------------------------------------
// bf16-split GEMM v4b: BK=32, 3-stage ring with DEPTH-2 prefetch (fixed race):
// issue tile it+2 into (it+2)%3 — never the stage being read (it%3).
// 8 warps, 64x32 warp tiles, 2 CTAs/SM, one barrier / 96 MMAs per warp.
// MODE 0: scatter Q(scaled)/K/V hi+lo head-major    MODE 1: fp32 C + bias
// ---------------------------------------------------------------------------
#define STG_B     32768                 // Ah 8K | Al 8K | Bh 8K | Bl 8K
#define GEMM_SMEM (3 * STG_B)           // 98304
#define NIT32     (GEMM_K / 32)         // 32

template<int MODE>
__global__ __launch_bounds__(256, 2) void gemm_bf16_kernel(
    const __nv_bfloat16* __restrict__ Ah, const __nv_bfloat16* __restrict__ Al,
    const __nv_bfloat16* __restrict__ Bh, const __nv_bfloat16* __restrict__ Bl,
    const float* __restrict__ bias, float* __restrict__ C, int Nfull)
{
    extern __shared__ __align__(16) uint8_t smg[];

    const int tid  = threadIdx.x;
    const int lane = tid & 31;
    const int wid  = tid >> 5;
    const int wm   = wid >> 2;
    const int wn   = wid & 3;
    const int m0   = blockIdx.y * 128;
    const int n0   = blockIdx.x * 128;
    const uint32_t uSm = smem_u32(smg);

    // loader: thread tid -> row tid>>1 (0..127), chunk pair (tid&1)*2
    const int lr = tid >> 1;
    const int lc2 = (tid & 1) * 2;
    const uint32_t lof0 = swz64(lr, lc2);
    const uint32_t lof1 = swz64(lr, lc2 + 1);

    auto issue = [&](int buf, int it) {
        const int k0 = it * 32;
        const uint32_t s = uSm + buf * STG_B;
        const __nv_bfloat16* pa_h = Ah + (size_t)(m0 + lr) * GEMM_K + k0 + lc2 * 8;
        const __nv_bfloat16* pa_l = Al + (size_t)(m0 + lr) * GEMM_K + k0 + lc2 * 8;
        const __nv_bfloat16* pb_h = Bh + (size_t)(n0 + lr) * GEMM_K + k0 + lc2 * 8;
        const __nv_bfloat16* pb_l = Bl + (size_t)(n0 + lr) * GEMM_K + k0 + lc2 * 8;
        cp16(s + lof0,          pa_h);   cp16(s + lof1,          pa_h + 8);
        cp16(s + 8192  + lof0,  pa_l);   cp16(s + 8192  + lof1,  pa_l + 8);
        cp16(s + 16384 + lof0,  pb_h);   cp16(s + 16384 + lof1,  pb_h + 8);
        cp16(s + 24576 + lof0,  pb_l);   cp16(s + 24576 + lof1,  pb_l + 8);
    };

    float acc[4][4][4];
#pragma unroll
    for (int t = 0; t < 4; t++)
#pragma unroll
        for (int u = 0; u < 4; u++)
#pragma unroll
            for (int e = 0; e < 4; e++) acc[t][u][e] = 0.f;

    issue(0, 0); CP_COMMIT();
    issue(1, 1); CP_COMMIT();

    const int arow = wm * 64 + (lane & 15);
    const int achk = lane >> 4;
    const int brow_base = wn * 32 + (lane & 7) + ((lane >> 4) << 3);
    const int bchk = (lane >> 3) & 1;

    for (int it = 0; it < NIT32; ++it) {
        if (it >= NIT32 - 1) { CP_WAIT0(); } else { CP_WAIT1(); }   // tile it ready
        __syncthreads();                      // all warps done reading (it-1)%3
        if (it + 2 < NIT32) { issue((it + 2) % 3, it + 2); CP_COMMIT(); }

        const uint32_t s   = uSm + (it % 3) * STG_B;
        const uint32_t bAh = s, bAl = s + 8192, bBh = s + 16384, bBl = s + 24576;

#pragma unroll
        for (int kc = 0; kc < 2; kc++) {
            uint32_t aH[4][4], aL[4][4], bH[8], bL[8];
#pragma unroll
            for (int t = 0; t < 4; t++) {
                const uint32_t off = swz64(arow + t * 16, 2 * kc + achk);
                ldsm4(bAh + off, aH[t]);
                ldsm4(bAl + off, aL[t]);
            }
#pragma unroll
            for (int p = 0; p < 2; p++) {
                const uint32_t off = swz64(brow_base + p * 16, 2 * kc + bchk);
                ldsm4(bBh + off, &bH[p * 4]);
                ldsm4(bBl + off, &bL[p * 4]);
            }
#pragma unroll
            for (int t = 0; t < 4; t++)
#pragma unroll
                for (int u = 0; u < 4; u++)
                    mma_bf16(acc[t][u], aH[t], &bH[(u >> 1) * 4 + (u & 1) * 2]);
#pragma unroll
            for (int t = 0; t < 4; t++)
#pragma unroll
                for (int u = 0; u < 4; u++)
                    mma_bf16(acc[t][u], aH[t], &bL[(u >> 1) * 4 + (u & 1) * 2]);
#pragma unroll
            for (int t = 0; t < 4; t++)
#pragma unroll
                for (int u = 0; u < 4; u++)
                    mma_bf16(acc[t][u], aL[t], &bH[(u >> 1) * 4 + (u & 1) * 2]);
        }
    }

    // ---- epilogue ----------------------------------------------------------
    const int mwarp = m0 + wm * 64;
    const int nwarp = n0 + wn * 32;
    const int g = lane >> 2, q = lane & 3;
#pragma unroll
    for (int u = 0; u < 4; u++) {
        const int n = nwarp + u * 8 + 2 * q;
        const float2 bv = *(const float2*)(bias + n);
#pragma unroll
        for (int t = 0; t < 4; t++) {
            const int m = mwarp + t * 16 + g;
            float2 v0 = make_float2(acc[t][u][0] + bv.x, acc[t][u][1] + bv.y);
            float2 v1 = make_float2(acc[t][u][2] + bv.x, acc[t][u][3] + bv.y);
            if (MODE == 1) {
                *(float2*)(C + (size_t)m * Nfull + n)       = v0;
                *(float2*)(C + (size_t)(m + 8) * Nfull + n) = v1;
            } else {
                const int which = n >> 10;
                const int e = n & 1023;
                const int h = e >> 6;
                const int d = e & 63;
                if (which == 0) { v0.x *= ATTN_SCALE; v0.y *= ATTN_SCALE;
                                  v1.x *= ATTN_SCALE; v1.y *= ATTN_SCALE; }
                __nv_bfloat16* dh = (which == 0) ? g_Qh : (which == 1) ? g_Kh : g_Vh;
                __nv_bfloat16* dl = (which == 0) ? g_Ql : (which == 1) ? g_Kl : g_Vl;
                const int b  = m >> 11;
                const size_t base = (((size_t)(b * NHEADS + h)) * NSEQ) * HDIM + d;
                const size_t o0 = base + (size_t)(m & 2047) * HDIM;
                const size_t o1 = base + (size_t)((m + 8) & 2047) * HDIM;
                *(uint32_t*)(dh + o0) = hipack(v0.x, v0.y);
                *(uint32_t*)(dl + o0) = lopack(v0.x, v0.y);
                *(uint32_t*)(dh + o1) = hipack(v1.x, v1.y);
                *(uint32_t*)(dl + o1) = lopack(v1.x, v1.y);
            }
        }
    }
}

// ---------------------------------------------------------------------------
// Flash attention v3.1 (unchanged from round 9)
// ---------------------------------------------------------------------------
#define FLASH_SMEM (32768 + 2*32768)   // Q(hi+lo 32KB) + 2 KV stages (32KB each)

__global__ __launch_bounds__(256, 2) void flash_mma_v3()
{
    extern __shared__ __align__(16) uint8_t sb[];
    const uint32_t uQh = smem_u32(sb);
    const uint32_t uQl = uQh + 16384;

    const int tid  = threadIdx.x;
    const int lane = tid & 31;
    const int wid  = tid >> 5;
    const int mt   = blockIdx.x;       // q tile (0..15)
    const int bh   = blockIdx.y;       // 0..31

    const size_t kvbase = (size_t)bh * NSEQ * HDIM;
    const __nv_bfloat16* Qhg = g_Qh + kvbase + (size_t)mt * 128 * HDIM;
    const __nv_bfloat16* Qlg = g_Ql + kvbase + (size_t)mt * 128 * HDIM;

    {
        const int r = tid >> 1;
        const int cb = (tid & 1) * 4;
#pragma unroll
        for (int c = 0; c < 4; c++) {
            cp16(uQh + swz128(r, cb + c), Qhg + (size_t)r * HDIM + (cb + c) * 8);
            cp16(uQl + swz128(r, cb + c), Qlg + (size_t)r * HDIM + (cb + c) * 8);
        }
    }

    auto issue_kv = [&](int t, int buf) {
        const uint32_t base = uQh + 32768 + buf * 32768;
        const __nv_bfloat16* Ks_h = g_Kh + kvbase + (size_t)t * 64 * HDIM;
        const __nv_bfloat16* Ks_l = g_Kl + kvbase + (size_t)t * 64 * HDIM;
        const __nv_bfloat16* Vs_h = g_Vh + kvbase + (size_t)t * 64 * HDIM;
        const __nv_bfloat16* Vs_l = g_Vl + kvbase + (size_t)t * 64 * HDIM;
#pragma unroll
        for (int i = 0; i < 2; i++) {
            const int id = tid + i * 256;
            const int r = id >> 3, c = id & 7;
            const uint32_t off = swz128(r, c);
            const size_t src = (size_t)r * HDIM + c * 8;
            cp16(base + off,          Ks_h + src);
            cp16(base + 8192 + off,   Ks_l + src);
            cp16(base + 16384 + off,  Vs_h + src);
            cp16(base + 24576 + off,  Vs_l + src);
        }
    };

    issue_kv(0, 0);
    CP_COMMIT();

    float of[8][4];
#pragma unroll
    for (int u = 0; u < 8; u++)
#pragma unroll
        for (int e = 0; e < 4; e++) of[u][e] = 0.f;
    float m0 = -1e30f, m1 = -1e30f, l0 = 0.f, l1 = 0.f;

    const int qrow = wid * 16 + (lane & 15);
    const int qsel = lane >> 4;
    const int brow = (lane & 7) + ((lane >> 4) << 3);
    const int bsel = (lane >> 3) & 1;
    const int vrow_l = lane & 15;
    const int vsel   = lane >> 4;

    for (int t = 0; t < NSEQ / 64; t++) {
        CP_WAIT0();
        __syncthreads();
        if (t + 1 < NSEQ / 64) { issue_kv(t + 1, (t + 1) & 1); CP_COMMIT(); }

        const uint32_t kvb = uQh + 32768 + (t & 1) * 32768;
        const uint32_t uKh = kvb, uKl = kvb + 8192;
        const uint32_t uVh = kvb + 16384, uVl = kvb + 24576;

        float sf[8][4];
#pragma unroll
        for (int u = 0; u < 8; u++)
#pragma unroll
            for (int e = 0; e < 4; e++) sf[u][e] = 0.f;

#pragma unroll
        for (int kc = 0; kc < 4; kc++) {
            uint32_t qh[4], ql[4];
            ldsm4(uQh + swz128(qrow, 2 * kc + qsel), qh);
            ldsm4(uQl + swz128(qrow, 2 * kc + qsel), ql);
            uint32_t bb[16];
#pragma unroll
            for (int nb = 0; nb < 4; nb++)
                ldsm4(uKh + swz128(nb * 16 + brow, 2 * kc + bsel), &bb[nb * 4]);
#pragma unroll
            for (int u = 0; u < 8; u++)
                mma_bf16(sf[u], qh, &bb[(u >> 1) * 4 + (u & 1) * 2]);
#pragma unroll
            for (int u = 0; u < 8; u++)
                mma_bf16(sf[u], ql, &bb[(u >> 1) * 4 + (u & 1) * 2]);
#pragma unroll
            for (int nb = 0; nb < 4; nb++)
                ldsm4(uKl + swz128(nb * 16 + brow, 2 * kc + bsel), &bb[nb * 4]);
#pragma unroll
            for (int u = 0; u < 8; u++)
                mma_bf16(sf[u], qh, &bb[(u >> 1) * 4 + (u & 1) * 2]);
        }

        {
            float mx0 = -1e30f, mx1 = -1e30f;
#pragma unroll
            for (int u = 0; u < 8; u++) {
                mx0 = fmaxf(mx0, fmaxf(sf[u][0], sf[u][1]));
                mx1 = fmaxf(mx1, fmaxf(sf[u][2], sf[u][3]));
            }
            mx0 = fmaxf(mx0, __shfl_xor_sync(0xffffffffu, mx0, 1));
            mx0 = fmaxf(mx0, __shfl_xor_sync(0xffffffffu, mx0, 2));
            mx1 = fmaxf(mx1, __shfl_xor_sync(0xffffffffu, mx1, 1));
            mx1 = fmaxf(mx1, __shfl_xor_sync(0xffffffffu, mx1, 2));

            float mn0 = fmaxf(m0, mx0), mn1 = fmaxf(m1, mx1);
            float c0 = __expf(m0 - mn0), c1 = __expf(m1 - mn1);
            m0 = mn0; m1 = mn1;
            float s0 = 0.f, s1 = 0.f;
#pragma unroll
            for (int u = 0; u < 8; u++) {
                float p0 = __expf(sf[u][0] - mn0);
                float p1 = __expf(sf[u][1] - mn0);
                float p2 = __expf(sf[u][2] - mn1);
                float p3 = __expf(sf[u][3] - mn1);
                s0 += p0 + p1; s1 += p2 + p3;
                sf[u][0] = p0; sf[u][1] = p1; sf[u][2] = p2; sf[u][3] = p3;
            }
            s0 += __shfl_xor_sync(0xffffffffu, s0, 1);
            s0 += __shfl_xor_sync(0xffffffffu, s0, 2);
            s1 += __shfl_xor_sync(0xffffffffu, s1, 1);
            s1 += __shfl_xor_sync(0xffffffffu, s1, 2);
            l0 = l0 * c0 + s0; l1 = l1 * c1 + s1;
#pragma unroll
            for (int u = 0; u < 8; u++) {
                of[u][0] *= c0; of[u][1] *= c0;
                of[u][2] *= c1; of[u][3] *= c1;
            }
        }

        uint32_t pH[4][4], pL[4][4];
#pragma unroll
        for (int kc = 0; kc < 4; kc++) {
            pH[kc][0] = hipack(sf[2*kc][0],   sf[2*kc][1]);
            pH[kc][1] = hipack(sf[2*kc][2],   sf[2*kc][3]);
            pH[kc][2] = hipack(sf[2*kc+1][0], sf[2*kc+1][1]);
            pH[kc][3] = hipack(sf[2*kc+1][2], sf[2*kc+1][3]);
            pL[kc][0] = lopack(sf[2*kc][0],   sf[2*kc][1]);
            pL[kc][1] = lopack(sf[2*kc][2],   sf[2*kc][3]);
            pL[kc][2] = lopack(sf[2*kc+1][0], sf[2*kc+1][1]);
            pL[kc][3] = lopack(sf[2*kc+1][2], sf[2*kc+1][3]);
        }

#pragma unroll
        for (int kc = 0; kc < 4; kc++) {
            uint32_t vv[16];
            const int row = 16 * kc + vrow_l;
#pragma unroll
            for (int vp = 0; vp < 4; vp++)
                ldsm4t(uVh + swz128(row, 2 * vp + vsel), &vv[vp * 4]);
#pragma unroll
            for (int u = 0; u < 8; u++)
                mma_bf16(of[u], pH[kc], &vv[(u >> 1) * 4 + (u & 1) * 2]);
#pragma unroll
            for (int u = 0; u < 8; u++)
                mma_bf16(of[u], pL[kc], &vv[(u >> 1) * 4 + (u & 1) * 2]);
#pragma unroll
            for (int vp = 0; vp < 4; vp++)
                ldsm4t(uVl + swz128(row, 2 * vp + vsel), &vv[vp * 4]);
#pragma unroll
            for (int u = 0; u < 8; u++)
                mma_bf16(of[u], pH[kc], &vv[(u >> 1) * 4 + (u & 1) * 2]);
        }
    }

    const float inv0 = __fdividef(1.f, l0);
    const float inv1 = __fdividef(1.f, l1);
    const int b = bh >> 4, h = bh & 15;
    const int g = lane >> 2, q = lane & 3;
    const int nrow = mt * 128 + wid * 16 + g;
    const size_t r0 = ((size_t)(b * NSEQ + nrow)) * EMBED + h * HDIM;
    const size_t r1 = r0 + (size_t)8 * EMBED;
#pragma unroll
    for (int u = 0; u < 8; u++) {
        const int col = 8 * u + 2 * q;
        float x0 = of[u][0] * inv0, y0 = of[u][1] * inv0;
        float x1 = of[u][2] * inv1, y1 = of[u][3] * inv1;
        *(uint32_t*)(g_AOh + r0 + col) = hipack(x0, y0);
        *(uint32_t*)(g_AOl + r0 + col) = lopack(x0, y0);
        *(uint32_t*)(g_AOh + r1 + col) = hipack(x1, y1);
        *(uint32_t*)(g_AOl + r1 + col) = lopack(x1, y1);
    }
}

// ---------------------------------------------------------------------------
extern "C" void kernel_launch(void* const* d_in, const int* in_sizes, int n_in,
                              void* d_out, int out_size)
{
    const float* x     = (const float*)d_in[0];
    const float* W_qkv = (const float*)d_in[1];
    const float* b_qkv = (const float*)d_in[2];
    const float* W_out = (const float*)d_in[3];
    const float* b_out = (const float*)d_in[4];
    float* out = (float*)d_out;

    __nv_bfloat16 *xh, *xl, *wqh, *wql, *woh, *wol, *aoh, *aol;
    cudaGetSymbolAddress((void**)&xh,  g_Xh);
    cudaGetSymbolAddress((void**)&xl,  g_Xl);
    cudaGetSymbolAddress((void**)&wqh, g_Wqh);
    cudaGetSymbolAddress((void**)&wql, g_Wql);
    cudaGetSymbolAddress((void**)&woh, g_Woh);
    cudaGetSymbolAddress((void**)&wol, g_Wol);
    cudaGetSymbolAddress((void**)&aoh, g_AOh);
    cudaGetSymbolAddress((void**)&aol, g_AOl);

    cudaFuncSetAttribute(flash_mma_v3,
                         cudaFuncAttributeMaxDynamicSharedMemorySize, FLASH_SMEM);
    cudaFuncSetAttribute(gemm_bf16_kernel<0>,
                         cudaFuncAttributeMaxDynamicSharedMemorySize, GEMM_SMEM);
    cudaFuncSetAttribute(gemm_bf16_kernel<1>,
                         cudaFuncAttributeMaxDynamicSharedMemorySize, GEMM_SMEM);

    // 0) one-time conversions
    convert_hl_kernel<<<(MTOT * EMBED / 4) / 256, 256>>>(x, xh, xl);
    transpose_hl_kernel<<<dim3(3*EMBED/32, EMBED/32), dim3(32, 8)>>>(W_qkv, wqh, wql, EMBED, 3*EMBED);
    transpose_hl_kernel<<<dim3(EMBED/32,   EMBED/32), dim3(32, 8)>>>(W_out, woh, wol, EMBED, EMBED);

    // 1) QKV projection -> Q(scaled)/K/V bf16 hi/lo head-major
    gemm_bf16_kernel<0><<<dim3(3*EMBED/128, MTOT/128), 256, GEMM_SMEM>>>(
        xh, xl, wqh, wql, b_qkv, nullptr, 3*EMBED);

    // 2) flash attention -> AO bf16 hi/lo
    flash_mma_v3<<<dim3(NSEQ/128, NB*NHEADS), 256, FLASH_SMEM>>>();

    // 3) output projection -> d_out (fp32)
    gemm_bf16_kernel<1><<<dim3(EMBED/128, MTOT/128), 256, GEMM_SMEM>>>(
        aoh, aol, woh, wol, b_out, out, EMBED);
}

// round 12
// speedup vs baseline: 1.0900x; 1.0004x over previous
#include <cuda_runtime.h>
#include <cuda_bf16.h>
#include <cstdint>
#include <math.h>

#define EMBED  1024
#define NHEADS 16
#define HDIM   64
#define NB     2
#define NSEQ   2048
#define MTOT   (NB*NSEQ)          // 4096
#define GEMM_K 1024
#define ATTN_SCALE 0.125f

// ---------------- scratch (__device__ globals) ------------------------------
__device__ __nv_bfloat16 g_Xh[MTOT*EMBED],      g_Xl[MTOT*EMBED];
__device__ __nv_bfloat16 g_Wqh[3*EMBED*EMBED],  g_Wql[3*EMBED*EMBED];
__device__ __nv_bfloat16 g_Woh[EMBED*EMBED],    g_Wol[EMBED*EMBED];
__device__ __nv_bfloat16 g_Qh[NB*NHEADS*NSEQ*HDIM], g_Ql[NB*NHEADS*NSEQ*HDIM];
__device__ __nv_bfloat16 g_Kh[NB*NHEADS*NSEQ*HDIM], g_Kl[NB*NHEADS*NSEQ*HDIM];
__device__ __nv_bfloat16 g_Vh[NB*NHEADS*NSEQ*HDIM], g_Vl[NB*NHEADS*NSEQ*HDIM];
__device__ __nv_bfloat16 g_AOh[MTOT*EMBED],     g_AOl[MTOT*EMBED];

// ---------------- helpers ---------------------------------------------------
__device__ __forceinline__ uint32_t smem_u32(const void* p) {
    uint32_t a;
    asm("{ .reg .u64 t; cvta.to.shared.u64 t, %1; cvt.u32.u64 %0, t; }"
        : "=r"(a) : "l"(p));
    return a;
}
__device__ __forceinline__ void ldsm4(uint32_t addr, uint32_t* r) {
    asm volatile("ldmatrix.sync.aligned.m8n8.x4.shared.b16 {%0,%1,%2,%3}, [%4];"
        : "=r"(r[0]), "=r"(r[1]), "=r"(r[2]), "=r"(r[3]) : "r"(addr));
}
__device__ __forceinline__ void ldsm4t(uint32_t addr, uint32_t* r) {
    asm volatile("ldmatrix.sync.aligned.m8n8.x4.trans.shared.b16 {%0,%1,%2,%3}, [%4];"
        : "=r"(r[0]), "=r"(r[1]), "=r"(r[2]), "=r"(r[3]) : "r"(addr));
}
__device__ __forceinline__ void mma_bf16(float* d, const uint32_t* a, const uint32_t* b) {
    asm volatile(
        "mma.sync.aligned.m16n8k16.row.col.f32.bf16.bf16.f32 "
        "{%0,%1,%2,%3},{%4,%5,%6,%7},{%8,%9},{%0,%1,%2,%3};"
        : "+f"(d[0]), "+f"(d[1]), "+f"(d[2]), "+f"(d[3])
        : "r"(a[0]), "r"(a[1]), "r"(a[2]), "r"(a[3]), "r"(b[0]), "r"(b[1]));
}
__device__ __forceinline__ void cp16(uint32_t s, const void* g) {
    asm volatile("cp.async.cg.shared.global [%0], [%1], 16;" :: "r"(s), "l"(g));
}
#define CP_COMMIT() asm volatile("cp.async.commit_group;" ::: "memory")
#define CP_WAIT0()  asm volatile("cp.async.wait_group 0;" ::: "memory")
#define CP_WAIT1()  asm volatile("cp.async.wait_group 1;" ::: "memory")

__device__ __forceinline__ uint32_t bits_bf162(__nv_bfloat162 h) {
    return *reinterpret_cast<uint32_t*>(&h);
}
__device__ __forceinline__ uint32_t hipack(float x, float y) {
    return (__float_as_uint(x) >> 16) | (__float_as_uint(y) & 0xffff0000u);
}
__device__ __forceinline__ uint32_t lopack(float x, float y) {
    float lx = x - __uint_as_float(__float_as_uint(x) & 0xffff0000u);
    float ly = y - __uint_as_float(__float_as_uint(y) & 0xffff0000u);
    return bits_bf162(__floats2bfloat162_rn(lx, ly));
}
__device__ __forceinline__ void cvt_hl(float4 v, uint2& h, uint2& l) {
    h.x = hipack(v.x, v.y); h.y = hipack(v.z, v.w);
    l.x = lopack(v.x, v.y); l.y = lopack(v.z, v.w);
}
// 128B-row swizzle (flash tiles): 16B chunk XOR row%8
__device__ __forceinline__ uint32_t swz128(int row, int chunk) {
    return (uint32_t)(row * 128 + ((chunk ^ (row & 7)) << 4));
}
// 64B-row swizzle (GEMM BK=32 tiles): chunk(0..3) XOR (row>>1)&3
__device__ __forceinline__ uint32_t swz64(int row, int chunk) {
    return (uint32_t)(row * 64 + ((chunk ^ ((row >> 1) & 3)) << 4));
}

// ---------------------------------------------------------------------------
// Pre-kernels: one-time conversions
// ---------------------------------------------------------------------------
__global__ void convert_hl_kernel(const float* __restrict__ S,
                                  __nv_bfloat16* __restrict__ Dh,
                                  __nv_bfloat16* __restrict__ Dl)
{
    int i = blockIdx.x * blockDim.x + threadIdx.x;   // float4 index
    float4 v = ((const float4*)S)[i];
    uint2 h, l; cvt_hl(v, h, l);
    ((uint2*)Dh)[i] = h;
    ((uint2*)Dl)[i] = l;
}

// src[K][N] f32 -> dst[N][K] bf16 hi/lo
__global__ void transpose_hl_kernel(const float* __restrict__ S,
                                    __nv_bfloat16* __restrict__ Dh,
                                    __nv_bfloat16* __restrict__ Dl,
                                    int K, int N)
{
    __shared__ float t[32][33];
    int bx = blockIdx.x * 32;   // N dim
    int by = blockIdx.y * 32;   // K dim
    int tx = threadIdx.x, ty = threadIdx.y;
#pragma unroll
    for (int j = 0; j < 32; j += 8)
        t[ty + j][tx] = S[(size_t)(by + ty + j) * N + bx + tx];
    __syncthreads();
#pragma unroll
    for (int j = 0; j < 32; j += 8) {
        float v = t[tx][ty + j];
        size_t idx = (size_t)(bx + ty + j) * K + by + tx;
        uint32_t u = __float_as_uint(v);
        ((uint16_t*)Dh)[idx] = (uint16_t)(u >> 16);
        float lr = v - __uint_as_float(u & 0xffff0000u);
        __nv_bfloat16 lb = __float2bfloat16(lr);
        ((uint16_t*)Dl)[idx] = *reinterpret_cast<uint16_t*>(&lb);
    }
}

// ---------------------------------------------------------------------------
// bf16-split GEMM v5: r11 skeleton (BK=32, 3-stage depth-2 ring, one barrier)
// with ROLLING ldsm/MMA interleave: term-1 frags load first, term-1 MMAs
// cover the term-2/3 frag loads. Register-neutral; bit-identical math.
// MODE 0: scatter Q(scaled)/K/V hi+lo head-major    MODE 1: fp32 C + bias
// ---------------------------------------------------------------------------
#define STG_B     32768                 // Ah 8K | Al 8K | Bh 8K | Bl 8K
#define GEMM_SMEM (3 * STG_B)           // 98304
#define NIT32     (GEMM_K / 32)         // 32

template<int MODE>
__global__ __launch_bounds__(256, 2) void gemm_bf16_kernel(
    const __nv_bfloat16* __restrict__ Ah, const __nv_bfloat16* __restrict__ Al,
    const __nv_bfloat16* __restrict__ Bh, const __nv_bfloat16* __restrict__ Bl,
    const float* __restrict__ bias, float* __restrict__ C, int Nfull)
{
    extern __shared__ __align__(16) uint8_t smg[];

    const int tid  = threadIdx.x;
    const int lane = tid & 31;
    const int wid  = tid >> 5;
    const int wm   = wid >> 2;
    const int wn   = wid & 3;
    const int m0   = blockIdx.y * 128;
    const int n0   = blockIdx.x * 128;
    const uint32_t uSm = smem_u32(smg);

    const int lr = tid >> 1;
    const int lc2 = (tid & 1) * 2;
    const uint32_t lof0 = swz64(lr, lc2);
    const uint32_t lof1 = swz64(lr, lc2 + 1);

    auto issue = [&](int buf, int it) {
        const int k0 = it * 32;
        const uint32_t s = uSm + buf * STG_B;
        const __nv_bfloat16* pa_h = Ah + (size_t)(m0 + lr) * GEMM_K + k0 + lc2 * 8;
        const __nv_bfloat16* pa_l = Al + (size_t)(m0 + lr) * GEMM_K + k0 + lc2 * 8;
        const __nv_bfloat16* pb_h = Bh + (size_t)(n0 + lr) * GEMM_K + k0 + lc2 * 8;
        const __nv_bfloat16* pb_l = Bl + (size_t)(n0 + lr) * GEMM_K + k0 + lc2 * 8;
        cp16(s + lof0,          pa_h);   cp16(s + lof1,          pa_h + 8);
        cp16(s + 8192  + lof0,  pa_l);   cp16(s + 8192  + lof1,  pa_l + 8);
        cp16(s + 16384 + lof0,  pb_h);   cp16(s + 16384 + lof1,  pb_h + 8);
        cp16(s + 24576 + lof0,  pb_l);   cp16(s + 24576 + lof1,  pb_l + 8);
    };

    float acc[4][4][4];
#pragma unroll
    for (int t = 0; t < 4; t++)
#pragma unroll
        for (int u = 0; u < 4; u++)
#pragma unroll
            for (int e = 0; e < 4; e++) acc[t][u][e] = 0.f;

    issue(0, 0); CP_COMMIT();
    issue(1, 1); CP_COMMIT();

    const int arow = wm * 64 + (lane & 15);
    const int achk = lane >> 4;
    const int brow_base = wn * 32 + (lane & 7) + ((lane >> 4) << 3);
    const int bchk = (lane >> 3) & 1;

    for (int it = 0; it < NIT32; ++it) {
        if (it >= NIT32 - 1) { CP_WAIT0(); } else { CP_WAIT1(); }
        __syncthreads();
        if (it + 2 < NIT32) { issue((it + 2) % 3, it + 2); CP_COMMIT(); }

        const uint32_t s   = uSm + (it % 3) * STG_B;
        const uint32_t bAh = s, bAl = s + 8192, bBh = s + 16384, bBl = s + 24576;

#pragma unroll
        for (int kc = 0; kc < 2; kc++) {
            uint32_t aH[4][4], aL[4][4], bH[8], bL[8];

            // ---- group-1 loads: exactly the term-1 operands ----
#pragma unroll
            for (int t = 0; t < 4; t++)
                ldsm4(bAh + swz64(arow + t * 16, 2 * kc + achk), aH[t]);
#pragma unroll
            for (int p = 0; p < 2; p++)
                ldsm4(bBh + swz64(brow_base + p * 16, 2 * kc + bchk), &bH[p * 4]);

            // ---- term 1 (aH x bH): 16 MMAs cover the group-2 ldsm below ----
#pragma unroll
            for (int t = 0; t < 4; t++)
#pragma unroll
                for (int u = 0; u < 4; u++)
                    mma_bf16(acc[t][u], aH[t], &bH[(u >> 1) * 4 + (u & 1) * 2]);

            // ---- group-2 loads under term-1's shadow ----
#pragma unroll
            for (int t = 0; t < 4; t++)
                ldsm4(bAl + swz64(arow + t * 16, 2 * kc + achk), aL[t]);
#pragma unroll
            for (int p = 0; p < 2; p++)
                ldsm4(bBl + swz64(brow_base + p * 16, 2 * kc + bchk), &bL[p * 4]);

            // ---- term 2 (aH x bL) ----
#pragma unroll
            for (int t = 0; t < 4; t++)
#pragma unroll
                for (int u = 0; u < 4; u++)
                    mma_bf16(acc[t][u], aH[t], &bL[(u >> 1) * 4 + (u & 1) * 2]);

            // ---- term 3 (aL x bH) ----
#pragma unroll
            for (int t = 0; t < 4; t++)
#pragma unroll
                for (int u = 0; u < 4; u++)
                    mma_bf16(acc[t][u], aL[t], &bH[(u >> 1) * 4 + (u & 1) * 2]);
        }
    }

    // ---- epilogue ----------------------------------------------------------
    const int mwarp = m0 + wm * 64;
    const int nwarp = n0 + wn * 32;
    const int g = lane >> 2, q = lane & 3;
#pragma unroll
    for (int u = 0; u < 4; u++) {
        const int n = nwarp + u * 8 + 2 * q;
        const float2 bv = *(const float2*)(bias + n);
#pragma unroll
        for (int t = 0; t < 4; t++) {
            const int m = mwarp + t * 16 + g;
            float2 v0 = make_float2(acc[t][u][0] + bv.x, acc[t][u][1] + bv.y);
            float2 v1 = make_float2(acc[t][u][2] + bv.x, acc[t][u][3] + bv.y);
            if (MODE == 1) {
                *(float2*)(C + (size_t)m * Nfull + n)       = v0;
                *(float2*)(C + (size_t)(m + 8) * Nfull + n) = v1;
            } else {
                const int which = n >> 10;
                const int e = n & 1023;
                const int h = e >> 6;
                const int d = e & 63;
                if (which == 0) { v0.x *= ATTN_SCALE; v0.y *= ATTN_SCALE;
                                  v1.x *= ATTN_SCALE; v1.y *= ATTN_SCALE; }
                __nv_bfloat16* dh = (which == 0) ? g_Qh : (which == 1) ? g_Kh : g_Vh;
                __nv_bfloat16* dl = (which == 0) ? g_Ql : (which == 1) ? g_Kl : g_Vl;
                const int b  = m >> 11;
                const size_t base = (((size_t)(b * NHEADS + h)) * NSEQ) * HDIM + d;
                const size_t o0 = base + (size_t)(m & 2047) * HDIM;
                const size_t o1 = base + (size_t)((m + 8) & 2047) * HDIM;
                *(uint32_t*)(dh + o0) = hipack(v0.x, v0.y);
                *(uint32_t*)(dl + o0) = lopack(v0.x, v0.y);
                *(uint32_t*)(dh + o1) = hipack(v1.x, v1.y);
                *(uint32_t*)(dl + o1) = lopack(v1.x, v1.y);
            }
        }
    }
}

// ---------------------------------------------------------------------------
// Flash attention v3.1 (unchanged from round 9/11)
// ---------------------------------------------------------------------------
#define FLASH_SMEM (32768 + 2*32768)   // Q(hi+lo 32KB) + 2 KV stages (32KB each)

__global__ __launch_bounds__(256, 2) void flash_mma_v3()
{
    extern __shared__ __align__(16) uint8_t sb[];
    const uint32_t uQh = smem_u32(sb);
    const uint32_t uQl = uQh + 16384;

    const int tid  = threadIdx.x;
    const int lane = tid & 31;
    const int wid  = tid >> 5;
    const int mt   = blockIdx.x;       // q tile (0..15)
    const int bh   = blockIdx.y;       // 0..31

    const size_t kvbase = (size_t)bh * NSEQ * HDIM;
    const __nv_bfloat16* Qhg = g_Qh + kvbase + (size_t)mt * 128 * HDIM;
    const __nv_bfloat16* Qlg = g_Ql + kvbase + (size_t)mt * 128 * HDIM;

    {
        const int r = tid >> 1;
        const int cb = (tid & 1) * 4;
#pragma unroll
        for (int c = 0; c < 4; c++) {
            cp16(uQh + swz128(r, cb + c), Qhg + (size_t)r * HDIM + (cb + c) * 8);
            cp16(uQl + swz128(r, cb + c), Qlg + (size_t)r * HDIM + (cb + c) * 8);
        }
    }

    auto issue_kv = [&](int t, int buf) {
        const uint32_t base = uQh + 32768 + buf * 32768;
        const __nv_bfloat16* Ks_h = g_Kh + kvbase + (size_t)t * 64 * HDIM;
        const __nv_bfloat16* Ks_l = g_Kl + kvbase + (size_t)t * 64 * HDIM;
        const __nv_bfloat16* Vs_h = g_Vh + kvbase + (size_t)t * 64 * HDIM;
        const __nv_bfloat16* Vs_l = g_Vl + kvbase + (size_t)t * 64 * HDIM;
#pragma unroll
        for (int i = 0; i < 2; i++) {
            const int id = tid + i * 256;
            const int r = id >> 3, c = id & 7;
            const uint32_t off = swz128(r, c);
            const size_t src = (size_t)r * HDIM + c * 8;
            cp16(base + off,          Ks_h + src);
            cp16(base + 8192 + off,   Ks_l + src);
            cp16(base + 16384 + off,  Vs_h + src);
            cp16(base + 24576 + off,  Vs_l + src);
        }
    };

    issue_kv(0, 0);
    CP_COMMIT();

    float of[8][4];
#pragma unroll
    for (int u = 0; u < 8; u++)
#pragma unroll
        for (int e = 0; e < 4; e++) of[u][e] = 0.f;
    float m0 = -1e30f, m1 = -1e30f, l0 = 0.f, l1 = 0.f;

    const int qrow = wid * 16 + (lane & 15);
    const int qsel = lane >> 4;
    const int brow = (lane & 7) + ((lane >> 4) << 3);
    const int bsel = (lane >> 3) & 1;
    const int vrow_l = lane & 15;
    const int vsel   = lane >> 4;

    for (int t = 0; t < NSEQ / 64; t++) {
        CP_WAIT0();
        __syncthreads();
        if (t + 1 < NSEQ / 64) { issue_kv(t + 1, (t + 1) & 1); CP_COMMIT(); }

        const uint32_t kvb = uQh + 32768 + (t & 1) * 32768;
        const uint32_t uKh = kvb, uKl = kvb + 8192;
        const uint32_t uVh = kvb + 16384, uVl = kvb + 24576;

        float sf[8][4];
#pragma unroll
        for (int u = 0; u < 8; u++)
#pragma unroll
            for (int e = 0; e < 4; e++) sf[u][e] = 0.f;

#pragma unroll
        for (int kc = 0; kc < 4; kc++) {
            uint32_t qh[4], ql[4];
            ldsm4(uQh + swz128(qrow, 2 * kc + qsel), qh);
            ldsm4(uQl + swz128(qrow, 2 * kc + qsel), ql);
            uint32_t bb[16];
#pragma unroll
            for (int nb = 0; nb < 4; nb++)
                ldsm4(uKh + swz128(nb * 16 + brow, 2 * kc + bsel), &bb[nb * 4]);
#pragma unroll
            for (int u = 0; u < 8; u++)
                mma_bf16(sf[u], qh, &bb[(u >> 1) * 4 + (u & 1) * 2]);
#pragma unroll
            for (int u = 0; u < 8; u++)
                mma_bf16(sf[u], ql, &bb[(u >> 1) * 4 + (u & 1) * 2]);
#pragma unroll
            for (int nb = 0; nb < 4; nb++)
                ldsm4(uKl + swz128(nb * 16 + brow, 2 * kc + bsel), &bb[nb * 4]);
#pragma unroll
            for (int u = 0; u < 8; u++)
                mma_bf16(sf[u], qh, &bb[(u >> 1) * 4 + (u & 1) * 2]);
        }

        {
            float mx0 = -1e30f, mx1 = -1e30f;
#pragma unroll
            for (int u = 0; u < 8; u++) {
                mx0 = fmaxf(mx0, fmaxf(sf[u][0], sf[u][1]));
                mx1 = fmaxf(mx1, fmaxf(sf[u][2], sf[u][3]));
            }
            mx0 = fmaxf(mx0, __shfl_xor_sync(0xffffffffu, mx0, 1));
            mx0 = fmaxf(mx0, __shfl_xor_sync(0xffffffffu, mx0, 2));
            mx1 = fmaxf(mx1, __shfl_xor_sync(0xffffffffu, mx1, 1));
            mx1 = fmaxf(mx1, __shfl_xor_sync(0xffffffffu, mx1, 2));

            float mn0 = fmaxf(m0, mx0), mn1 = fmaxf(m1, mx1);
            float c0 = __expf(m0 - mn0), c1 = __expf(m1 - mn1);
            m0 = mn0; m1 = mn1;
            float s0 = 0.f, s1 = 0.f;
#pragma unroll
            for (int u = 0; u < 8; u++) {
                float p0 = __expf(sf[u][0] - mn0);
                float p1 = __expf(sf[u][1] - mn0);
                float p2 = __expf(sf[u][2] - mn1);
                float p3 = __expf(sf[u][3] - mn1);
                s0 += p0 + p1; s1 += p2 + p3;
                sf[u][0] = p0; sf[u][1] = p1; sf[u][2] = p2; sf[u][3] = p3;
            }
            s0 += __shfl_xor_sync(0xffffffffu, s0, 1);
            s0 += __shfl_xor_sync(0xffffffffu, s0, 2);
            s1 += __shfl_xor_sync(0xffffffffu, s1, 1);
            s1 += __shfl_xor_sync(0xffffffffu, s1, 2);
            l0 = l0 * c0 + s0; l1 = l1 * c1 + s1;
#pragma unroll
            for (int u = 0; u < 8; u++) {
                of[u][0] *= c0; of[u][1] *= c0;
                of[u][2] *= c1; of[u][3] *= c1;
            }
        }

        uint32_t pH[4][4], pL[4][4];
#pragma unroll
        for (int kc = 0; kc < 4; kc++) {
            pH[kc][0] = hipack(sf[2*kc][0],   sf[2*kc][1]);
            pH[kc][1] = hipack(sf[2*kc][2],   sf[2*kc][3]);
            pH[kc][2] = hipack(sf[2*kc+1][0], sf[2*kc+1][1]);
            pH[kc][3] = hipack(sf[2*kc+1][2], sf[2*kc+1][3]);
            pL[kc][0] = lopack(sf[2*kc][0],   sf[2*kc][1]);
            pL[kc][1] = lopack(sf[2*kc][2],   sf[2*kc][3]);
            pL[kc][2] = lopack(sf[2*kc+1][0], sf[2*kc+1][1]);
            pL[kc][3] = lopack(sf[2*kc+1][2], sf[2*kc+1][3]);
        }

#pragma unroll
        for (int kc = 0; kc < 4; kc++) {
            uint32_t vv[16];
            const int row = 16 * kc + vrow_l;
#pragma unroll
            for (int vp = 0; vp < 4; vp++)
                ldsm4t(uVh + swz128(row, 2 * vp + vsel), &vv[vp * 4]);
#pragma unroll
            for (int u = 0; u < 8; u++)
                mma_bf16(of[u], pH[kc], &vv[(u >> 1) * 4 + (u & 1) * 2]);
#pragma unroll
            for (int u = 0; u < 8; u++)
                mma_bf16(of[u], pL[kc], &vv[(u >> 1) * 4 + (u & 1) * 2]);
#pragma unroll
            for (int vp = 0; vp < 4; vp++)
                ldsm4t(uVl + swz128(row, 2 * vp + vsel), &vv[vp * 4]);
#pragma unroll
            for (int u = 0; u < 8; u++)
                mma_bf16(of[u], pH[kc], &vv[(u >> 1) * 4 + (u & 1) * 2]);
        }
    }

    const float inv0 = __fdividef(1.f, l0);
    const float inv1 = __fdividef(1.f, l1);
    const int b = bh >> 4, h = bh & 15;
    const int g = lane >> 2, q = lane & 3;
    const int nrow = mt * 128 + wid * 16 + g;
    const size_t r0 = ((size_t)(b * NSEQ + nrow)) * EMBED + h * HDIM;
    const size_t r1 = r0 + (size_t)8 * EMBED;
#pragma unroll
    for (int u = 0; u < 8; u++) {
        const int col = 8 * u + 2 * q;
        float x0 = of[u][0] * inv0, y0 = of[u][1] * inv0;
        float x1 = of[u][2] * inv1, y1 = of[u][3] * inv1;
        *(uint32_t*)(g_AOh + r0 + col) = hipack(x0, y0);
        *(uint32_t*)(g_AOl + r0 + col) = lopack(x0, y0);
        *(uint32_t*)(g_AOh + r1 + col) = hipack(x1, y1);
        *(uint32_t*)(g_AOl + r1 + col) = lopack(x1, y1);
    }
}

// ---------------------------------------------------------------------------
extern "C" void kernel_launch(void* const* d_in, const int* in_sizes, int n_in,
                              void* d_out, int out_size)
{
    const float* x     = (const float*)d_in[0];
    const float* W_qkv = (const float*)d_in[1];
    const float* b_qkv = (const float*)d_in[2];
    const float* W_out = (const float*)d_in[3];
    const float* b_out = (const float*)d_in[4];
    float* out = (float*)d_out;

    __nv_bfloat16 *xh, *xl, *wqh, *wql, *woh, *wol, *aoh, *aol;
    cudaGetSymbolAddress((void**)&xh,  g_Xh);
    cudaGetSymbolAddress((void**)&xl,  g_Xl);
    cudaGetSymbolAddress((void**)&wqh, g_Wqh);
    cudaGetSymbolAddress((void**)&wql, g_Wql);
    cudaGetSymbolAddress((void**)&woh, g_Woh);
    cudaGetSymbolAddress((void**)&wol, g_Wol);
    cudaGetSymbolAddress((void**)&aoh, g_AOh);
    cudaGetSymbolAddress((void**)&aol, g_AOl);

    cudaFuncSetAttribute(flash_mma_v3,
                         cudaFuncAttributeMaxDynamicSharedMemorySize, FLASH_SMEM);
    cudaFuncSetAttribute(gemm_bf16_kernel<0>,
                         cudaFuncAttributeMaxDynamicSharedMemorySize, GEMM_SMEM);
    cudaFuncSetAttribute(gemm_bf16_kernel<1>,
                         cudaFuncAttributeMaxDynamicSharedMemorySize, GEMM_SMEM);

    // 0) one-time conversions
    convert_hl_kernel<<<(MTOT * EMBED / 4) / 256, 256>>>(x, xh, xl);
    transpose_hl_kernel<<<dim3(3*EMBED/32, EMBED/32), dim3(32, 8)>>>(W_qkv, wqh, wql, EMBED, 3*EMBED);
    transpose_hl_kernel<<<dim3(EMBED/32,   EMBED/32), dim3(32, 8)>>>(W_out, woh, wol, EMBED, EMBED);

    // 1) QKV projection -> Q(scaled)/K/V bf16 hi/lo head-major
    gemm_bf16_kernel<0><<<dim3(3*EMBED/128, MTOT/128), 256, GEMM_SMEM>>>(
        xh, xl, wqh, wql, b_qkv, nullptr, 3*EMBED);

    // 2) flash attention -> AO bf16 hi/lo
    flash_mma_v3<<<dim3(NSEQ/128, NB*NHEADS), 256, FLASH_SMEM>>>();

    // 3) output projection -> d_out (fp32)
    gemm_bf16_kernel<1><<<dim3(EMBED/128, MTOT/128), 256, GEMM_SMEM>>>(
        aoh, aol, woh, wol, b_out, out, EMBED);
}

// round 13
// speedup vs baseline: 1.1068x; 1.0154x over previous
#include <cuda_runtime.h>
#include <cuda_bf16.h>
#include <cstdint>
#include <math.h>

#define EMBED  1024
#define NHEADS 16
#define HDIM   64
#define NB     2
#define NSEQ   2048
#define MTOT   (NB*NSEQ)          // 4096
#define GEMM_K 1024
#define ATTN_SCALE 0.125f

// ---------------- scratch (__device__ globals) ------------------------------
__device__ __nv_bfloat16 g_Xh[MTOT*EMBED],      g_Xl[MTOT*EMBED];
__device__ __nv_bfloat16 g_Wqh[3*EMBED*EMBED],  g_Wql[3*EMBED*EMBED];
__device__ __nv_bfloat16 g_Woh[EMBED*EMBED],    g_Wol[EMBED*EMBED];
__device__ __nv_bfloat16 g_Qh[NB*NHEADS*NSEQ*HDIM], g_Ql[NB*NHEADS*NSEQ*HDIM];
__device__ __nv_bfloat16 g_Kh[NB*NHEADS*NSEQ*HDIM], g_Kl[NB*NHEADS*NSEQ*HDIM];
__device__ __nv_bfloat16 g_Vh[NB*NHEADS*NSEQ*HDIM], g_Vl[NB*NHEADS*NSEQ*HDIM];
__device__ __nv_bfloat16 g_AOh[MTOT*EMBED],     g_AOl[MTOT*EMBED];

// ---------------- helpers ---------------------------------------------------
__device__ __forceinline__ uint32_t smem_u32(const void* p) {
    uint32_t a;
    asm("{ .reg .u64 t; cvta.to.shared.u64 t, %1; cvt.u32.u64 %0, t; }"
        : "=r"(a) : "l"(p));
    return a;
}
__device__ __forceinline__ void ldsm4(uint32_t addr, uint32_t* r) {
    asm volatile("ldmatrix.sync.aligned.m8n8.x4.shared.b16 {%0,%1,%2,%3}, [%4];"
        : "=r"(r[0]), "=r"(r[1]), "=r"(r[2]), "=r"(r[3]) : "r"(addr));
}
__device__ __forceinline__ void ldsm4t(uint32_t addr, uint32_t* r) {
    asm volatile("ldmatrix.sync.aligned.m8n8.x4.trans.shared.b16 {%0,%1,%2,%3}, [%4];"
        : "=r"(r[0]), "=r"(r[1]), "=r"(r[2]), "=r"(r[3]) : "r"(addr));
}
__device__ __forceinline__ void mma_bf16(float* d, const uint32_t* a, const uint32_t* b) {
    asm volatile(
        "mma.sync.aligned.m16n8k16.row.col.f32.bf16.bf16.f32 "
        "{%0,%1,%2,%3},{%4,%5,%6,%7},{%8,%9},{%0,%1,%2,%3};"
        : "+f"(d[0]), "+f"(d[1]), "+f"(d[2]), "+f"(d[3])
        : "r"(a[0]), "r"(a[1]), "r"(a[2]), "r"(a[3]), "r"(b[0]), "r"(b[1]));
}
__device__ __forceinline__ void cp16(uint32_t s, const void* g) {
    asm volatile("cp.async.cg.shared.global [%0], [%1], 16;" :: "r"(s), "l"(g));
}
#define CP_COMMIT() asm volatile("cp.async.commit_group;" ::: "memory")
#define CP_WAIT0()  asm volatile("cp.async.wait_group 0;" ::: "memory")
#define CP_WAIT1()  asm volatile("cp.async.wait_group 1;" ::: "memory")

__device__ __forceinline__ uint32_t bits_bf162(__nv_bfloat162 h) {
    return *reinterpret_cast<uint32_t*>(&h);
}
__device__ __forceinline__ uint32_t hipack(float x, float y) {
    return (__float_as_uint(x) >> 16) | (__float_as_uint(y) & 0xffff0000u);
}
__device__ __forceinline__ uint32_t lopack(float x, float y) {
    float lx = x - __uint_as_float(__float_as_uint(x) & 0xffff0000u);
    float ly = y - __uint_as_float(__float_as_uint(y) & 0xffff0000u);
    return bits_bf162(__floats2bfloat162_rn(lx, ly));
}
__device__ __forceinline__ void cvt_hl(float4 v, uint2& h, uint2& l) {
    h.x = hipack(v.x, v.y); h.y = hipack(v.z, v.w);
    l.x = lopack(v.x, v.y); l.y = lopack(v.z, v.w);
}
// 128B-row swizzle (flash tiles): 16B chunk XOR row%8
__device__ __forceinline__ uint32_t swz128(int row, int chunk) {
    return (uint32_t)(row * 128 + ((chunk ^ (row & 7)) << 4));
}
// 32B-row GEMM tile swizzle: chunk(0/1) XOR (row>>2)&1
__device__ __forceinline__ uint32_t tile_off(int r, int chunk) {
    return (uint32_t)(r * 32 + ((chunk ^ ((r >> 2) & 1)) << 4));
}

// ---------------------------------------------------------------------------
// Pre-kernels: one-time conversions
// ---------------------------------------------------------------------------
__global__ void convert_hl_kernel(const float* __restrict__ S,
                                  __nv_bfloat16* __restrict__ Dh,
                                  __nv_bfloat16* __restrict__ Dl)
{
    int i = blockIdx.x * blockDim.x + threadIdx.x;   // float4 index
    float4 v = ((const float4*)S)[i];
    uint2 h, l; cvt_hl(v, h, l);
    ((uint2*)Dh)[i] = h;
    ((uint2*)Dl)[i] = l;
}

// src[K][N] f32 -> dst[N][K] bf16 hi/lo
__global__ void transpose_hl_kernel(const float* __restrict__ S,
                                    __nv_bfloat16* __restrict__ Dh,
                                    __nv_bfloat16* __restrict__ Dl,
                                    int K, int N)
{
    __shared__ float t[32][33];
    int bx = blockIdx.x * 32;   // N dim
    int by = blockIdx.y * 32;   // K dim
    int tx = threadIdx.x, ty = threadIdx.y;
#pragma unroll
    for (int j = 0; j < 32; j += 8)
        t[ty + j][tx] = S[(size_t)(by + ty + j) * N + bx + tx];
    __syncthreads();
#pragma unroll
    for (int j = 0; j < 32; j += 8) {
        float v = t[tx][ty + j];
        size_t idx = (size_t)(bx + ty + j) * K + by + tx;
        uint32_t u = __float_as_uint(v);
        ((uint16_t*)Dh)[idx] = (uint16_t)(u >> 16);
        float lr = v - __uint_as_float(u & 0xffff0000u);
        __nv_bfloat16 lb = __float2bfloat16(lr);
        ((uint16_t*)Dl)[idx] = *reinterpret_cast<uint16_t*>(&lb);
    }
}

// ---------------------------------------------------------------------------
// bf16-split GEMM v6: SMALL-CTA topology. 128 threads (4 warps), CTA tile
// 128x64, warp tile 64x32 (same per-warp stream as r9/r11), BK=16, 3-stage
// depth-2 ring, one barrier/iter, 4 CTAs/SM = 16 warps in 4 independent
// barrier domains.
// MODE 0: scatter Q(scaled)/K/V hi+lo head-major    MODE 1: fp32 C + bias
// ---------------------------------------------------------------------------
#define STG_B     12288                 // Ah 4K | Al 4K | Bh 2K | Bl 2K
#define GEMM_SMEM (3 * STG_B)           // 36864
#define NIT16     (GEMM_K / 16)         // 64

template<int MODE>
__global__ __launch_bounds__(128, 4) void gemm_bf16_kernel(
    const __nv_bfloat16* __restrict__ Ah, const __nv_bfloat16* __restrict__ Al,
    const __nv_bfloat16* __restrict__ Bh, const __nv_bfloat16* __restrict__ Bl,
    const float* __restrict__ bias, float* __restrict__ C, int Nfull)
{
    extern __shared__ __align__(16) uint8_t smg[];

    const int tid  = threadIdx.x;        // 0..127
    const int lane = tid & 31;
    const int wid  = tid >> 5;           // 0..3
    const int wm   = wid >> 1;           // 0..1 (64 rows)
    const int wn   = wid & 1;            // 0..1 (32 cols)
    const int m0   = blockIdx.y * 128;
    const int n0   = blockIdx.x * 64;
    const uint32_t uSm = smem_u32(smg);

    // loaders: A 128x16 (256 cp16: 2/thread), B 64x16 (128 cp16: 1/thread)
    const int ar0 = tid >> 1,  ac0 = tid & 1;            // A part 0
    const int ar1 = (tid + 128) >> 1;                    // A part 1 (same chunk)
    const int br  = tid >> 1;                            // only tid<128 all load? 128 thr, 64 rows x 2 chunks
    const int bc  = tid & 1;
    const uint32_t aof0 = tile_off(ar0, ac0);
    const uint32_t aof1 = tile_off(ar1, ac0);
    const uint32_t bof  = tile_off(br, bc);              // br in 0..63

    auto issue = [&](int buf, int it) {
        const int k0 = it * 16;
        const uint32_t s = uSm + buf * STG_B;
        cp16(s + aof0,        Ah + (size_t)(m0 + ar0) * GEMM_K + k0 + ac0 * 8);
        cp16(s + aof1,        Ah + (size_t)(m0 + ar1) * GEMM_K + k0 + ac0 * 8);
        cp16(s + 4096 + aof0, Al + (size_t)(m0 + ar0) * GEMM_K + k0 + ac0 * 8);
        cp16(s + 4096 + aof1, Al + (size_t)(m0 + ar1) * GEMM_K + k0 + ac0 * 8);
        cp16(s + 8192 + bof,  Bh + (size_t)(n0 + br) * GEMM_K + k0 + bc * 8);
        cp16(s + 10240 + bof, Bl + (size_t)(n0 + br) * GEMM_K + k0 + bc * 8);
    };

    float acc[4][4][4];
#pragma unroll
    for (int t = 0; t < 4; t++)
#pragma unroll
        for (int u = 0; u < 4; u++)
#pragma unroll
            for (int e = 0; e < 4; e++) acc[t][u][e] = 0.f;

    issue(0, 0); CP_COMMIT();
    issue(1, 1); CP_COMMIT();

    const int arow = wm * 64 + (lane & 15);
    const int achk = lane >> 4;
    const int brow_base = wn * 32 + (lane & 7) + ((lane >> 4) << 3);
    const int bchk = (lane >> 3) & 1;

    for (int it = 0; it < NIT16; ++it) {
        if (it >= NIT16 - 1) { CP_WAIT0(); } else { CP_WAIT1(); }
        __syncthreads();                       // 4-warp barrier only
        if (it + 2 < NIT16) { issue((it + 2) % 3, it + 2); CP_COMMIT(); }

        const uint32_t s   = uSm + (it % 3) * STG_B;
        const uint32_t bAh = s, bAl = s + 4096, bBh = s + 8192, bBl = s + 10240;

        uint32_t aH[4][4], aL[4][4], bH[8], bL[8];
#pragma unroll
        for (int t = 0; t < 4; t++) {
            const uint32_t off = tile_off(arow + t * 16, achk);
            ldsm4(bAh + off, aH[t]);
            ldsm4(bAl + off, aL[t]);
        }
#pragma unroll
        for (int p = 0; p < 2; p++) {
            const uint32_t off = tile_off(brow_base + p * 16, bchk);
            ldsm4(bBh + off, &bH[p * 4]);
            ldsm4(bBl + off, &bL[p * 4]);
        }
#pragma unroll
        for (int t = 0; t < 4; t++)
#pragma unroll
            for (int u = 0; u < 4; u++)
                mma_bf16(acc[t][u], aH[t], &bH[(u >> 1) * 4 + (u & 1) * 2]);
#pragma unroll
        for (int t = 0; t < 4; t++)
#pragma unroll
            for (int u = 0; u < 4; u++)
                mma_bf16(acc[t][u], aH[t], &bL[(u >> 1) * 4 + (u & 1) * 2]);
#pragma unroll
        for (int t = 0; t < 4; t++)
#pragma unroll
            for (int u = 0; u < 4; u++)
                mma_bf16(acc[t][u], aL[t], &bH[(u >> 1) * 4 + (u & 1) * 2]);
    }

    // ---- epilogue ----------------------------------------------------------
    const int mwarp = m0 + wm * 64;
    const int nwarp = n0 + wn * 32;
    const int g = lane >> 2, q = lane & 3;
#pragma unroll
    for (int u = 0; u < 4; u++) {
        const int n = nwarp + u * 8 + 2 * q;
        const float2 bv = *(const float2*)(bias + n);
#pragma unroll
        for (int t = 0; t < 4; t++) {
            const int m = mwarp + t * 16 + g;
            float2 v0 = make_float2(acc[t][u][0] + bv.x, acc[t][u][1] + bv.y);
            float2 v1 = make_float2(acc[t][u][2] + bv.x, acc[t][u][3] + bv.y);
            if (MODE == 1) {
                *(float2*)(C + (size_t)m * Nfull + n)       = v0;
                *(float2*)(C + (size_t)(m + 8) * Nfull + n) = v1;
            } else {
                const int which = n >> 10;
                const int e = n & 1023;
                const int h = e >> 6;
                const int d = e & 63;
                if (which == 0) { v0.x *= ATTN_SCALE; v0.y *= ATTN_SCALE;
                                  v1.x *= ATTN_SCALE; v1.y *= ATTN_SCALE; }
                __nv_bfloat16* dh = (which == 0) ? g_Qh : (which == 1) ? g_Kh : g_Vh;
                __nv_bfloat16* dl = (which == 0) ? g_Ql : (which == 1) ? g_Kl : g_Vl;
                const int b  = m >> 11;
                const size_t base = (((size_t)(b * NHEADS + h)) * NSEQ) * HDIM + d;
                const size_t o0 = base + (size_t)(m & 2047) * HDIM;
                const size_t o1 = base + (size_t)((m + 8) & 2047) * HDIM;
                *(uint32_t*)(dh + o0) = hipack(v0.x, v0.y);
                *(uint32_t*)(dl + o0) = lopack(v0.x, v0.y);
                *(uint32_t*)(dh + o1) = hipack(v1.x, v1.y);
                *(uint32_t*)(dl + o1) = lopack(v1.x, v1.y);
            }
        }
    }
}

// ---------------------------------------------------------------------------
// Flash attention v3.1 (unchanged from round 9/11/12)
// ---------------------------------------------------------------------------
#define FLASH_SMEM (32768 + 2*32768)   // Q(hi+lo 32KB) + 2 KV stages (32KB each)

__global__ __launch_bounds__(256, 2) void flash_mma_v3()
{
    extern __shared__ __align__(16) uint8_t sb[];
    const uint32_t uQh = smem_u32(sb);
    const uint32_t uQl = uQh + 16384;

    const int tid  = threadIdx.x;
    const int lane = tid & 31;
    const int wid  = tid >> 5;
    const int mt   = blockIdx.x;       // q tile (0..15)
    const int bh   = blockIdx.y;       // 0..31

    const size_t kvbase = (size_t)bh * NSEQ * HDIM;
    const __nv_bfloat16* Qhg = g_Qh + kvbase + (size_t)mt * 128 * HDIM;
    const __nv_bfloat16* Qlg = g_Ql + kvbase + (size_t)mt * 128 * HDIM;

    {
        const int r = tid >> 1;
        const int cb = (tid & 1) * 4;
#pragma unroll
        for (int c = 0; c < 4; c++) {
            cp16(uQh + swz128(r, cb + c), Qhg + (size_t)r * HDIM + (cb + c) * 8);
            cp16(uQl + swz128(r, cb + c), Qlg + (size_t)r * HDIM + (cb + c) * 8);
        }
    }

    auto issue_kv = [&](int t, int buf) {
        const uint32_t base = uQh + 32768 + buf * 32768;
        const __nv_bfloat16* Ks_h = g_Kh + kvbase + (size_t)t * 64 * HDIM;
        const __nv_bfloat16* Ks_l = g_Kl + kvbase + (size_t)t * 64 * HDIM;
        const __nv_bfloat16* Vs_h = g_Vh + kvbase + (size_t)t * 64 * HDIM;
        const __nv_bfloat16* Vs_l = g_Vl + kvbase + (size_t)t * 64 * HDIM;
#pragma unroll
        for (int i = 0; i < 2; i++) {
            const int id = tid + i * 256;
            const int r = id >> 3, c = id & 7;
            const uint32_t off = swz128(r, c);
            const size_t src = (size_t)r * HDIM + c * 8;
            cp16(base + off,          Ks_h + src);
            cp16(base + 8192 + off,   Ks_l + src);
            cp16(base + 16384 + off,  Vs_h + src);
            cp16(base + 24576 + off,  Vs_l + src);
        }
    };

    issue_kv(0, 0);
    CP_COMMIT();

    float of[8][4];
#pragma unroll
    for (int u = 0; u < 8; u++)
#pragma unroll
        for (int e = 0; e < 4; e++) of[u][e] = 0.f;
    float m0 = -1e30f, m1 = -1e30f, l0 = 0.f, l1 = 0.f;

    const int qrow = wid * 16 + (lane & 15);
    const int qsel = lane >> 4;
    const int brow = (lane & 7) + ((lane >> 4) << 3);
    const int bsel = (lane >> 3) & 1;
    const int vrow_l = lane & 15;
    const int vsel   = lane >> 4;

    for (int t = 0; t < NSEQ / 64; t++) {
        CP_WAIT0();
        __syncthreads();
        if (t + 1 < NSEQ / 64) { issue_kv(t + 1, (t + 1) & 1); CP_COMMIT(); }

        const uint32_t kvb = uQh + 32768 + (t & 1) * 32768;
        const uint32_t uKh = kvb, uKl = kvb + 8192;
        const uint32_t uVh = kvb + 16384, uVl = kvb + 24576;

        float sf[8][4];
#pragma unroll
        for (int u = 0; u < 8; u++)
#pragma unroll
            for (int e = 0; e < 4; e++) sf[u][e] = 0.f;

#pragma unroll
        for (int kc = 0; kc < 4; kc++) {
            uint32_t qh[4], ql[4];
            ldsm4(uQh + swz128(qrow, 2 * kc + qsel), qh);
            ldsm4(uQl + swz128(qrow, 2 * kc + qsel), ql);
            uint32_t bb[16];
#pragma unroll
            for (int nb = 0; nb < 4; nb++)
                ldsm4(uKh + swz128(nb * 16 + brow, 2 * kc + bsel), &bb[nb * 4]);
#pragma unroll
            for (int u = 0; u < 8; u++)
                mma_bf16(sf[u], qh, &bb[(u >> 1) * 4 + (u & 1) * 2]);
#pragma unroll
            for (int u = 0; u < 8; u++)
                mma_bf16(sf[u], ql, &bb[(u >> 1) * 4 + (u & 1) * 2]);
#pragma unroll
            for (int nb = 0; nb < 4; nb++)
                ldsm4(uKl + swz128(nb * 16 + brow, 2 * kc + bsel), &bb[nb * 4]);
#pragma unroll
            for (int u = 0; u < 8; u++)
                mma_bf16(sf[u], qh, &bb[(u >> 1) * 4 + (u & 1) * 2]);
        }

        {
            float mx0 = -1e30f, mx1 = -1e30f;
#pragma unroll
            for (int u = 0; u < 8; u++) {
                mx0 = fmaxf(mx0, fmaxf(sf[u][0], sf[u][1]));
                mx1 = fmaxf(mx1, fmaxf(sf[u][2], sf[u][3]));
            }
            mx0 = fmaxf(mx0, __shfl_xor_sync(0xffffffffu, mx0, 1));
            mx0 = fmaxf(mx0, __shfl_xor_sync(0xffffffffu, mx0, 2));
            mx1 = fmaxf(mx1, __shfl_xor_sync(0xffffffffu, mx1, 1));
            mx1 = fmaxf(mx1, __shfl_xor_sync(0xffffffffu, mx1, 2));

            float mn0 = fmaxf(m0, mx0), mn1 = fmaxf(m1, mx1);
            float c0 = __expf(m0 - mn0), c1 = __expf(m1 - mn1);
            m0 = mn0; m1 = mn1;
            float s0 = 0.f, s1 = 0.f;
#pragma unroll
            for (int u = 0; u < 8; u++) {
                float p0 = __expf(sf[u][0] - mn0);
                float p1 = __expf(sf[u][1] - mn0);
                float p2 = __expf(sf[u][2] - mn1);
                float p3 = __expf(sf[u][3] - mn1);
                s0 += p0 + p1; s1 += p2 + p3;
                sf[u][0] = p0; sf[u][1] = p1; sf[u][2] = p2; sf[u][3] = p3;
            }
            s0 += __shfl_xor_sync(0xffffffffu, s0, 1);
            s0 += __shfl_xor_sync(0xffffffffu, s0, 2);
            s1 += __shfl_xor_sync(0xffffffffu, s1, 1);
            s1 += __shfl_xor_sync(0xffffffffu, s1, 2);
            l0 = l0 * c0 + s0; l1 = l1 * c1 + s1;
#pragma unroll
            for (int u = 0; u < 8; u++) {
                of[u][0] *= c0; of[u][1] *= c0;
                of[u][2] *= c1; of[u][3] *= c1;
            }
        }

        uint32_t pH[4][4], pL[4][4];
#pragma unroll
        for (int kc = 0; kc < 4; kc++) {
            pH[kc][0] = hipack(sf[2*kc][0],   sf[2*kc][1]);
            pH[kc][1] = hipack(sf[2*kc][2],   sf[2*kc][3]);
            pH[kc][2] = hipack(sf[2*kc+1][0], sf[2*kc+1][1]);
            pH[kc][3] = hipack(sf[2*kc+1][2], sf[2*kc+1][3]);
            pL[kc][0] = lopack(sf[2*kc][0],   sf[2*kc][1]);
            pL[kc][1] = lopack(sf[2*kc][2],   sf[2*kc][3]);
            pL[kc][2] = lopack(sf[2*kc+1][0], sf[2*kc+1][1]);
            pL[kc][3] = lopack(sf[2*kc+1][2], sf[2*kc+1][3]);
        }

#pragma unroll
        for (int kc = 0; kc < 4; kc++) {
            uint32_t vv[16];
            const int row = 16 * kc + vrow_l;
#pragma unroll
            for (int vp = 0; vp < 4; vp++)
                ldsm4t(uVh + swz128(row, 2 * vp + vsel), &vv[vp * 4]);
#pragma unroll
            for (int u = 0; u < 8; u++)
                mma_bf16(of[u], pH[kc], &vv[(u >> 1) * 4 + (u & 1) * 2]);
#pragma unroll
            for (int u = 0; u < 8; u++)
                mma_bf16(of[u], pL[kc], &vv[(u >> 1) * 4 + (u & 1) * 2]);
#pragma unroll
            for (int vp = 0; vp < 4; vp++)
                ldsm4t(uVl + swz128(row, 2 * vp + vsel), &vv[vp * 4]);
#pragma unroll
            for (int u = 0; u < 8; u++)
                mma_bf16(of[u], pH[kc], &vv[(u >> 1) * 4 + (u & 1) * 2]);
        }
    }

    const float inv0 = __fdividef(1.f, l0);
    const float inv1 = __fdividef(1.f, l1);
    const int b = bh >> 4, h = bh & 15;
    const int g = lane >> 2, q = lane & 3;
    const int nrow = mt * 128 + wid * 16 + g;
    const size_t r0 = ((size_t)(b * NSEQ + nrow)) * EMBED + h * HDIM;
    const size_t r1 = r0 + (size_t)8 * EMBED;
#pragma unroll
    for (int u = 0; u < 8; u++) {
        const int col = 8 * u + 2 * q;
        float x0 = of[u][0] * inv0, y0 = of[u][1] * inv0;
        float x1 = of[u][2] * inv1, y1 = of[u][3] * inv1;
        *(uint32_t*)(g_AOh + r0 + col) = hipack(x0, y0);
        *(uint32_t*)(g_AOl + r0 + col) = lopack(x0, y0);
        *(uint32_t*)(g_AOh + r1 + col) = hipack(x1, y1);
        *(uint32_t*)(g_AOl + r1 + col) = lopack(x1, y1);
    }
}

// ---------------------------------------------------------------------------
extern "C" void kernel_launch(void* const* d_in, const int* in_sizes, int n_in,
                              void* d_out, int out_size)
{
    const float* x     = (const float*)d_in[0];
    const float* W_qkv = (const float*)d_in[1];
    const float* b_qkv = (const float*)d_in[2];
    const float* W_out = (const float*)d_in[3];
    const float* b_out = (const float*)d_in[4];
    float* out = (float*)d_out;

    __nv_bfloat16 *xh, *xl, *wqh, *wql, *woh, *wol, *aoh, *aol;
    cudaGetSymbolAddress((void**)&xh,  g_Xh);
    cudaGetSymbolAddress((void**)&xl,  g_Xl);
    cudaGetSymbolAddress((void**)&wqh, g_Wqh);
    cudaGetSymbolAddress((void**)&wql, g_Wql);
    cudaGetSymbolAddress((void**)&woh, g_Woh);
    cudaGetSymbolAddress((void**)&wol, g_Wol);
    cudaGetSymbolAddress((void**)&aoh, g_AOh);
    cudaGetSymbolAddress((void**)&aol, g_AOl);

    cudaFuncSetAttribute(flash_mma_v3,
                         cudaFuncAttributeMaxDynamicSharedMemorySize, FLASH_SMEM);
    cudaFuncSetAttribute(gemm_bf16_kernel<0>,
                         cudaFuncAttributeMaxDynamicSharedMemorySize, GEMM_SMEM);
    cudaFuncSetAttribute(gemm_bf16_kernel<1>,
                         cudaFuncAttributeMaxDynamicSharedMemorySize, GEMM_SMEM);

    // 0) one-time conversions
    convert_hl_kernel<<<(MTOT * EMBED / 4) / 256, 256>>>(x, xh, xl);
    transpose_hl_kernel<<<dim3(3*EMBED/32, EMBED/32), dim3(32, 8)>>>(W_qkv, wqh, wql, EMBED, 3*EMBED);
    transpose_hl_kernel<<<dim3(EMBED/32,   EMBED/32), dim3(32, 8)>>>(W_out, woh, wol, EMBED, EMBED);

    // 1) QKV projection -> Q(scaled)/K/V bf16 hi/lo head-major
    gemm_bf16_kernel<0><<<dim3(3*EMBED/64, MTOT/128), 128, GEMM_SMEM>>>(
        xh, xl, wqh, wql, b_qkv, nullptr, 3*EMBED);

    // 2) flash attention -> AO bf16 hi/lo
    flash_mma_v3<<<dim3(NSEQ/128, NB*NHEADS), 256, FLASH_SMEM>>>();

    // 3) output projection -> d_out (fp32)
    gemm_bf16_kernel<1><<<dim3(EMBED/64, MTOT/128), 128, GEMM_SMEM>>>(
        aoh, aol, woh, wol, b_out, out, EMBED);
}

// round 14
// speedup vs baseline: 1.4158x; 1.2793x over previous
#include <cuda_runtime.h>
#include <cuda_fp16.h>
#include <cstdint>
#include <math.h>

#define EMBED  1024
#define NHEADS 16
#define HDIM   64
#define NB     2
#define NSEQ   2048
#define MTOT   (NB*NSEQ)          // 4096
#define GEMM_K 1024
#define ATTN_SCALE 0.125f

// ---------------- scratch (__device__ globals) ------------------------------
__device__ __half g_Xh[MTOT*EMBED],  g_Xl[MTOT*EMBED];
__device__ __half g_Wq[3*EMBED*EMBED];           // W_qkv^T single fp16
__device__ __half g_Wo[EMBED*EMBED];             // W_out^T single fp16
__device__ __half g_Qh[NB*NHEADS*NSEQ*HDIM], g_Ql[NB*NHEADS*NSEQ*HDIM];
__device__ __half g_K[NB*NHEADS*NSEQ*HDIM];      // single fp16
__device__ __half g_V[NB*NHEADS*NSEQ*HDIM];      // single fp16
__device__ __half g_AOh[MTOT*EMBED], g_AOl[MTOT*EMBED];

// ---------------- helpers ---------------------------------------------------
__device__ __forceinline__ uint32_t smem_u32(const void* p) {
    uint32_t a;
    asm("{ .reg .u64 t; cvta.to.shared.u64 t, %1; cvt.u32.u64 %0, t; }"
        : "=r"(a) : "l"(p));
    return a;
}
__device__ __forceinline__ void ldsm4(uint32_t addr, uint32_t* r) {
    asm volatile("ldmatrix.sync.aligned.m8n8.x4.shared.b16 {%0,%1,%2,%3}, [%4];"
        : "=r"(r[0]), "=r"(r[1]), "=r"(r[2]), "=r"(r[3]) : "r"(addr));
}
__device__ __forceinline__ void ldsm4t(uint32_t addr, uint32_t* r) {
    asm volatile("ldmatrix.sync.aligned.m8n8.x4.trans.shared.b16 {%0,%1,%2,%3}, [%4];"
        : "=r"(r[0]), "=r"(r[1]), "=r"(r[2]), "=r"(r[3]) : "r"(addr));
}
__device__ __forceinline__ void mma_f16(float* d, const uint32_t* a, const uint32_t* b) {
    asm volatile(
        "mma.sync.aligned.m16n8k16.row.col.f32.f16.f16.f32 "
        "{%0,%1,%2,%3},{%4,%5,%6,%7},{%8,%9},{%0,%1,%2,%3};"
        : "+f"(d[0]), "+f"(d[1]), "+f"(d[2]), "+f"(d[3])
        : "r"(a[0]), "r"(a[1]), "r"(a[2]), "r"(a[3]), "r"(b[0]), "r"(b[1]));
}
__device__ __forceinline__ void cp16(uint32_t s, const void* g) {
    asm volatile("cp.async.cg.shared.global [%0], [%1], 16;" :: "r"(s), "l"(g));
}
#define CP_COMMIT() asm volatile("cp.async.commit_group;" ::: "memory")
#define CP_WAIT0()  asm volatile("cp.async.wait_group 0;" ::: "memory")
#define CP_WAIT1()  asm volatile("cp.async.wait_group 1;" ::: "memory")

__device__ __forceinline__ uint32_t h2bits(__half2 h) {
    return *reinterpret_cast<uint32_t*>(&h);
}
// fp16 rn pack of (x,y)
__device__ __forceinline__ uint32_t hpack(float x, float y) {
    return h2bits(__floats2half2_rn(x, y));
}
// fp16 residual pack: l = rn(v - rn16(v))
__device__ __forceinline__ uint32_t lpack(float x, float y) {
    __half hx = __float2half_rn(x), hy = __float2half_rn(y);
    float rx = x - __half2float(hx), ry = y - __half2float(hy);
    return h2bits(__floats2half2_rn(rx, ry));
}
// 128B-row swizzle: 16B chunk XOR row%8
__device__ __forceinline__ uint32_t swz128(int row, int chunk) {
    return (uint32_t)(row * 128 + ((chunk ^ (row & 7)) << 4));
}
// 32B-row GEMM tile swizzle: chunk(0/1) XOR (row>>2)&1
__device__ __forceinline__ uint32_t tile_off(int r, int chunk) {
    return (uint32_t)(r * 32 + ((chunk ^ ((r >> 2) & 1)) << 4));
}

// ---------------------------------------------------------------------------
// Pre-kernels
// ---------------------------------------------------------------------------
__global__ void convert_hl_kernel(const float* __restrict__ S,
                                  __half* __restrict__ Dh,
                                  __half* __restrict__ Dl)
{
    int i = blockIdx.x * blockDim.x + threadIdx.x;   // float4 index
    float4 v = ((const float4*)S)[i];
    uint2 h, l;
    h.x = hpack(v.x, v.y); h.y = hpack(v.z, v.w);
    l.x = lpack(v.x, v.y); l.y = lpack(v.z, v.w);
    ((uint2*)Dh)[i] = h;
    ((uint2*)Dl)[i] = l;
}

// src[K][N] f32 -> dst[N][K] single fp16
__global__ void transpose_h_kernel(const float* __restrict__ S,
                                   __half* __restrict__ D, int K, int N)
{
    __shared__ float t[32][33];
    int bx = blockIdx.x * 32;   // N dim
    int by = blockIdx.y * 32;   // K dim
    int tx = threadIdx.x, ty = threadIdx.y;
#pragma unroll
    for (int j = 0; j < 32; j += 8)
        t[ty + j][tx] = S[(size_t)(by + ty + j) * N + bx + tx];
    __syncthreads();
#pragma unroll
    for (int j = 0; j < 32; j += 8)
        D[(size_t)(bx + ty + j) * K + by + tx] = __float2half_rn(t[tx][ty + j]);
}

// ---------------------------------------------------------------------------
// fp16 2-term GEMM: C = (Ah+Al)[M,1024] @ B[N,1024]^T + bias
// Small-CTA topology (r13): 128 thr, CTA 128x64, warp 64x32, BK=16,
// 3-stage depth-2 ring, 4 CTAs/SM.
// MODE 0: scatter Q(scaled, hi/lo) / K,V (single) head-major   MODE 1: f32 C
// ---------------------------------------------------------------------------
#define STG_B     10240                 // Ah 4K | Al 4K | B 2K
#define GEMM_SMEM (3 * STG_B)           // 30720
#define NIT16     (GEMM_K / 16)         // 64

template<int MODE>
__global__ __launch_bounds__(128, 4) void gemm_f16_kernel(
    const __half* __restrict__ Ah, const __half* __restrict__ Al,
    const __half* __restrict__ B,
    const float* __restrict__ bias, float* __restrict__ C, int Nfull)
{
    extern __shared__ __align__(16) uint8_t smg[];

    const int tid  = threadIdx.x;        // 0..127
    const int lane = tid & 31;
    const int wid  = tid >> 5;           // 0..3
    const int wm   = wid >> 1;           // 0..1 (64 rows)
    const int wn   = wid & 1;            // 0..1 (32 cols)
    const int m0   = blockIdx.y * 128;
    const int n0   = blockIdx.x * 64;
    const uint32_t uSm = smem_u32(smg);

    const int ar0 = tid >> 1,  ac0 = tid & 1;
    const int ar1 = (tid + 128) >> 1;
    const int br  = tid >> 1,  bc  = tid & 1;
    const uint32_t aof0 = tile_off(ar0, ac0);
    const uint32_t aof1 = tile_off(ar1, ac0);
    const uint32_t bof  = tile_off(br, bc);

    auto issue = [&](int buf, int it) {
        const int k0 = it * 16;
        const uint32_t s = uSm + buf * STG_B;
        cp16(s + aof0,        Ah + (size_t)(m0 + ar0) * GEMM_K + k0 + ac0 * 8);
        cp16(s + aof1,        Ah + (size_t)(m0 + ar1) * GEMM_K + k0 + ac0 * 8);
        cp16(s + 4096 + aof0, Al + (size_t)(m0 + ar0) * GEMM_K + k0 + ac0 * 8);
        cp16(s + 4096 + aof1, Al + (size_t)(m0 + ar1) * GEMM_K + k0 + ac0 * 8);
        cp16(s + 8192 + bof,  B  + (size_t)(n0 + br) * GEMM_K + k0 + bc * 8);
    };

    float acc[4][4][4];
#pragma unroll
    for (int t = 0; t < 4; t++)
#pragma unroll
        for (int u = 0; u < 4; u++)
#pragma unroll
            for (int e = 0; e < 4; e++) acc[t][u][e] = 0.f;

    issue(0, 0); CP_COMMIT();
    issue(1, 1); CP_COMMIT();

    const int arow = wm * 64 + (lane & 15);
    const int achk = lane >> 4;
    const int brow_base = wn * 32 + (lane & 7) + ((lane >> 4) << 3);
    const int bchk = (lane >> 3) & 1;

    for (int it = 0; it < NIT16; ++it) {
        if (it >= NIT16 - 1) { CP_WAIT0(); } else { CP_WAIT1(); }
        __syncthreads();
        if (it + 2 < NIT16) { issue((it + 2) % 3, it + 2); CP_COMMIT(); }

        const uint32_t s   = uSm + (it % 3) * STG_B;
        const uint32_t bAh = s, bAl = s + 4096, bB = s + 8192;

        uint32_t aH[4][4], aL[4][4], bF[8];
#pragma unroll
        for (int t = 0; t < 4; t++) {
            const uint32_t off = tile_off(arow + t * 16, achk);
            ldsm4(bAh + off, aH[t]);
            ldsm4(bAl + off, aL[t]);
        }
#pragma unroll
        for (int p = 0; p < 2; p++)
            ldsm4(bB + tile_off(brow_base + p * 16, bchk), &bF[p * 4]);

        // term 1: Ah x B
#pragma unroll
        for (int t = 0; t < 4; t++)
#pragma unroll
            for (int u = 0; u < 4; u++)
                mma_f16(acc[t][u], aH[t], &bF[(u >> 1) * 4 + (u & 1) * 2]);
        // term 2: Al x B
#pragma unroll
        for (int t = 0; t < 4; t++)
#pragma unroll
            for (int u = 0; u < 4; u++)
                mma_f16(acc[t][u], aL[t], &bF[(u >> 1) * 4 + (u & 1) * 2]);
    }

    // ---- epilogue ----------------------------------------------------------
    const int mwarp = m0 + wm * 64;
    const int nwarp = n0 + wn * 32;
    const int g = lane >> 2, q = lane & 3;
#pragma unroll
    for (int u = 0; u < 4; u++) {
        const int n = nwarp + u * 8 + 2 * q;
        const float2 bv = *(const float2*)(bias + n);
#pragma unroll
        for (int t = 0; t < 4; t++) {
            const int m = mwarp + t * 16 + g;
            float2 v0 = make_float2(acc[t][u][0] + bv.x, acc[t][u][1] + bv.y);
            float2 v1 = make_float2(acc[t][u][2] + bv.x, acc[t][u][3] + bv.y);
            if (MODE == 1) {
                *(float2*)(C + (size_t)m * Nfull + n)       = v0;
                *(float2*)(C + (size_t)(m + 8) * Nfull + n) = v1;
            } else {
                const int which = n >> 10;
                const int e = n & 1023;
                const int h = e >> 6;
                const int d = e & 63;
                const int b  = m >> 11;
                const size_t base = (((size_t)(b * NHEADS + h)) * NSEQ) * HDIM + d;
                const size_t o0 = base + (size_t)(m & 2047) * HDIM;
                const size_t o1 = base + (size_t)((m + 8) & 2047) * HDIM;
                if (which == 0) {
                    v0.x *= ATTN_SCALE; v0.y *= ATTN_SCALE;
                    v1.x *= ATTN_SCALE; v1.y *= ATTN_SCALE;
                    *(uint32_t*)(g_Qh + o0) = hpack(v0.x, v0.y);
                    *(uint32_t*)(g_Ql + o0) = lpack(v0.x, v0.y);
                    *(uint32_t*)(g_Qh + o1) = hpack(v1.x, v1.y);
                    *(uint32_t*)(g_Ql + o1) = lpack(v1.x, v1.y);
                } else {
                    __half* dst = (which == 1) ? g_K : g_V;
                    *(uint32_t*)(dst + o0) = hpack(v0.x, v0.y);
                    *(uint32_t*)(dst + o1) = hpack(v1.x, v1.y);
                }
            }
        }
    }
}

// ---------------------------------------------------------------------------
// Flash attention v4: fp16 2-term. Q hi/lo smem-resident; K,V single fp16,
// cp.async 2-stage. 256 thr, 128 q-rows, kv tile 64, 2 CTAs/SM.
// ---------------------------------------------------------------------------
#define FLASH_SMEM (32768 + 2*16384)   // Q(hi+lo 32KB) + 2 KV stages (16KB each)

__global__ __launch_bounds__(256, 2) void flash_mma_v4()
{
    extern __shared__ __align__(16) uint8_t sb[];
    const uint32_t uQh = smem_u32(sb);
    const uint32_t uQl = uQh + 16384;

    const int tid  = threadIdx.x;
    const int lane = tid & 31;
    const int wid  = tid >> 5;
    const int mt   = blockIdx.x;       // q tile (0..15)
    const int bh   = blockIdx.y;       // 0..31

    const size_t kvbase = (size_t)bh * NSEQ * HDIM;
    const __half* Qhg = g_Qh + kvbase + (size_t)mt * 128 * HDIM;
    const __half* Qlg = g_Ql + kvbase + (size_t)mt * 128 * HDIM;

    // Q load: 128 rows x 8 chunks (128B rows) x (hi,lo)
    {
        const int r = tid >> 1;
        const int cb = (tid & 1) * 4;
#pragma unroll
        for (int c = 0; c < 4; c++) {
            cp16(uQh + swz128(r, cb + c), Qhg + (size_t)r * HDIM + (cb + c) * 8);
            cp16(uQl + swz128(r, cb + c), Qlg + (size_t)r * HDIM + (cb + c) * 8);
        }
    }

    auto issue_kv = [&](int t, int buf) {
        const uint32_t base = uQh + 32768 + buf * 16384;
        const __half* Ks = g_K + kvbase + (size_t)t * 64 * HDIM;
        const __half* Vs = g_V + kvbase + (size_t)t * 64 * HDIM;
#pragma unroll
        for (int i = 0; i < 2; i++) {
            const int id = tid + i * 256;       // 0..511
            const int r = id >> 3, c = id & 7;
            const uint32_t off = swz128(r, c);
            const size_t src = (size_t)r * HDIM + c * 8;
            cp16(base + off,        Ks + src);
            cp16(base + 8192 + off, Vs + src);
        }
    };

    issue_kv(0, 0);
    CP_COMMIT();

    float of[8][4];
#pragma unroll
    for (int u = 0; u < 8; u++)
#pragma unroll
        for (int e = 0; e < 4; e++) of[u][e] = 0.f;
    float m0 = -1e30f, m1 = -1e30f, l0 = 0.f, l1 = 0.f;

    const int qrow = wid * 16 + (lane & 15);
    const int qsel = lane >> 4;
    const int brow = (lane & 7) + ((lane >> 4) << 3);
    const int bsel = (lane >> 3) & 1;
    const int vrow_l = lane & 15;
    const int vsel   = lane >> 4;

    for (int t = 0; t < NSEQ / 64; t++) {
        CP_WAIT0();
        __syncthreads();
        if (t + 1 < NSEQ / 64) { issue_kv(t + 1, (t + 1) & 1); CP_COMMIT(); }

        const uint32_t kvb = uQh + 32768 + (t & 1) * 16384;
        const uint32_t uK = kvb, uV = kvb + 8192;

        // ---- S = Q @ K^T (2-term fp16) ------------------------------------
        float sf[8][4];
#pragma unroll
        for (int u = 0; u < 8; u++)
#pragma unroll
            for (int e = 0; e < 4; e++) sf[u][e] = 0.f;

#pragma unroll
        for (int kc = 0; kc < 4; kc++) {
            uint32_t qh[4], ql[4];
            ldsm4(uQh + swz128(qrow, 2 * kc + qsel), qh);
            ldsm4(uQl + swz128(qrow, 2 * kc + qsel), ql);
            uint32_t bb[16];
#pragma unroll
            for (int nb = 0; nb < 4; nb++)
                ldsm4(uK + swz128(nb * 16 + brow, 2 * kc + bsel), &bb[nb * 4]);
#pragma unroll
            for (int u = 0; u < 8; u++)
                mma_f16(sf[u], qh, &bb[(u >> 1) * 4 + (u & 1) * 2]);
#pragma unroll
            for (int u = 0; u < 8; u++)
                mma_f16(sf[u], ql, &bb[(u >> 1) * 4 + (u & 1) * 2]);
        }

        // ---- online softmax ----------------------------------------------
        {
            float mx0 = -1e30f, mx1 = -1e30f;
#pragma unroll
            for (int u = 0; u < 8; u++) {
                mx0 = fmaxf(mx0, fmaxf(sf[u][0], sf[u][1]));
                mx1 = fmaxf(mx1, fmaxf(sf[u][2], sf[u][3]));
            }
            mx0 = fmaxf(mx0, __shfl_xor_sync(0xffffffffu, mx0, 1));
            mx0 = fmaxf(mx0, __shfl_xor_sync(0xffffffffu, mx0, 2));
            mx1 = fmaxf(mx1, __shfl_xor_sync(0xffffffffu, mx1, 1));
            mx1 = fmaxf(mx1, __shfl_xor_sync(0xffffffffu, mx1, 2));

            float mn0 = fmaxf(m0, mx0), mn1 = fmaxf(m1, mx1);
            float c0 = __expf(m0 - mn0), c1 = __expf(m1 - mn1);
            m0 = mn0; m1 = mn1;
            float s0 = 0.f, s1 = 0.f;
#pragma unroll
            for (int u = 0; u < 8; u++) {
                float p0 = __expf(sf[u][0] - mn0);
                float p1 = __expf(sf[u][1] - mn0);
                float p2 = __expf(sf[u][2] - mn1);
                float p3 = __expf(sf[u][3] - mn1);
                s0 += p0 + p1; s1 += p2 + p3;
                sf[u][0] = p0; sf[u][1] = p1; sf[u][2] = p2; sf[u][3] = p3;
            }
            s0 += __shfl_xor_sync(0xffffffffu, s0, 1);
            s0 += __shfl_xor_sync(0xffffffffu, s0, 2);
            s1 += __shfl_xor_sync(0xffffffffu, s1, 1);
            s1 += __shfl_xor_sync(0xffffffffu, s1, 2);
            l0 = l0 * c0 + s0; l1 = l1 * c1 + s1;
#pragma unroll
            for (int u = 0; u < 8; u++) {
                of[u][0] *= c0; of[u][1] *= c0;
                of[u][2] *= c1; of[u][3] *= c1;
            }
        }

        // ---- P frags (fp16 hi/lo in registers) ----------------------------
        uint32_t pH[4][4], pL[4][4];
#pragma unroll
        for (int kc = 0; kc < 4; kc++) {
            pH[kc][0] = hpack(sf[2*kc][0],   sf[2*kc][1]);
            pH[kc][1] = hpack(sf[2*kc][2],   sf[2*kc][3]);
            pH[kc][2] = hpack(sf[2*kc+1][0], sf[2*kc+1][1]);
            pH[kc][3] = hpack(sf[2*kc+1][2], sf[2*kc+1][3]);
            pL[kc][0] = lpack(sf[2*kc][0],   sf[2*kc][1]);
            pL[kc][1] = lpack(sf[2*kc][2],   sf[2*kc][3]);
            pL[kc][2] = lpack(sf[2*kc+1][0], sf[2*kc+1][1]);
            pL[kc][3] = lpack(sf[2*kc+1][2], sf[2*kc+1][3]);
        }

        // ---- O += P @ V (2-term fp16; V single via ldmatrix.trans) --------
#pragma unroll
        for (int kc = 0; kc < 4; kc++) {
            uint32_t vv[16];
            const int row = 16 * kc + vrow_l;
#pragma unroll
            for (int vp = 0; vp < 4; vp++)
                ldsm4t(uV + swz128(row, 2 * vp + vsel), &vv[vp * 4]);
#pragma unroll
            for (int u = 0; u < 8; u++)
                mma_f16(of[u], pH[kc], &vv[(u >> 1) * 4 + (u & 1) * 2]);
#pragma unroll
            for (int u = 0; u < 8; u++)
                mma_f16(of[u], pL[kc], &vv[(u >> 1) * 4 + (u & 1) * 2]);
        }
    }

    // ---- epilogue: normalize, write AO as fp16 hi/lo [B*N, E] --------------
    const float inv0 = __fdividef(1.f, l0);
    const float inv1 = __fdividef(1.f, l1);
    const int b = bh >> 4, h = bh & 15;
    const int g = lane >> 2, q = lane & 3;
    const int nrow = mt * 128 + wid * 16 + g;
    const size_t r0 = ((size_t)(b * NSEQ + nrow)) * EMBED + h * HDIM;
    const size_t r1 = r0 + (size_t)8 * EMBED;
#pragma unroll
    for (int u = 0; u < 8; u++) {
        const int col = 8 * u + 2 * q;
        float x0 = of[u][0] * inv0, y0 = of[u][1] * inv0;
        float x1 = of[u][2] * inv1, y1 = of[u][3] * inv1;
        *(uint32_t*)(g_AOh + r0 + col) = hpack(x0, y0);
        *(uint32_t*)(g_AOl + r0 + col) = lpack(x0, y0);
        *(uint32_t*)(g_AOh + r1 + col) = hpack(x1, y1);
        *(uint32_t*)(g_AOl + r1 + col) = lpack(x1, y1);
    }
}

// ---------------------------------------------------------------------------
extern "C" void kernel_launch(void* const* d_in, const int* in_sizes, int n_in,
                              void* d_out, int out_size)
{
    const float* x     = (const float*)d_in[0];
    const float* W_qkv = (const float*)d_in[1];
    const float* b_qkv = (const float*)d_in[2];
    const float* W_out = (const float*)d_in[3];
    const float* b_out = (const float*)d_in[4];
    float* out = (float*)d_out;

    __half *xh, *xl, *wq, *wo, *aoh, *aol;
    cudaGetSymbolAddress((void**)&xh,  g_Xh);
    cudaGetSymbolAddress((void**)&xl,  g_Xl);
    cudaGetSymbolAddress((void**)&wq,  g_Wq);
    cudaGetSymbolAddress((void**)&wo,  g_Wo);
    cudaGetSymbolAddress((void**)&aoh, g_AOh);
    cudaGetSymbolAddress((void**)&aol, g_AOl);

    cudaFuncSetAttribute(flash_mma_v4,
                         cudaFuncAttributeMaxDynamicSharedMemorySize, FLASH_SMEM);
    cudaFuncSetAttribute(gemm_f16_kernel<0>,
                         cudaFuncAttributeMaxDynamicSharedMemorySize, GEMM_SMEM);
    cudaFuncSetAttribute(gemm_f16_kernel<1>,
                         cudaFuncAttributeMaxDynamicSharedMemorySize, GEMM_SMEM);

    // 0) one-time conversions
    convert_hl_kernel<<<(MTOT * EMBED / 4) / 256, 256>>>(x, xh, xl);
    transpose_h_kernel<<<dim3(3*EMBED/32, EMBED/32), dim3(32, 8)>>>(W_qkv, wq, EMBED, 3*EMBED);
    transpose_h_kernel<<<dim3(EMBED/32,   EMBED/32), dim3(32, 8)>>>(W_out, wo, EMBED, EMBED);

    // 1) QKV projection -> Q(scaled hi/lo) / K,V single fp16 head-major
    gemm_f16_kernel<0><<<dim3(3*EMBED/64, MTOT/128), 128, GEMM_SMEM>>>(
        xh, xl, wq, b_qkv, nullptr, 3*EMBED);

    // 2) flash attention -> AO fp16 hi/lo
    flash_mma_v4<<<dim3(NSEQ/128, NB*NHEADS), 256, FLASH_SMEM>>>();

    // 3) output projection -> d_out (fp32)
    gemm_f16_kernel<1><<<dim3(EMBED/64, MTOT/128), 128, GEMM_SMEM>>>(
        aoh, aol, wo, b_out, out, EMBED);
}

// round 15
// speedup vs baseline: 1.7842x; 1.2602x over previous
#include <cuda_runtime.h>
#include <cuda_fp16.h>
#include <cstdint>
#include <math.h>

#define EMBED  1024
#define NHEADS 16
#define HDIM   64
#define NB     2
#define NSEQ   2048
#define MTOT   (NB*NSEQ)          // 4096
#define GEMM_K 1024
#define ATTN_SCALE 0.125f

// ---------------- scratch (__device__ globals) ------------------------------
__device__ __half g_Xh[MTOT*EMBED],  g_Xl[MTOT*EMBED];
__device__ __half g_Wq[3*EMBED*EMBED];           // W_qkv^T single fp16
__device__ __half g_Wo[EMBED*EMBED];             // W_out^T single fp16
__device__ __half g_Q[NB*NHEADS*NSEQ*HDIM];      // single fp16 (scaled)
__device__ __half g_K[NB*NHEADS*NSEQ*HDIM];      // single fp16
__device__ __half g_V[NB*NHEADS*NSEQ*HDIM];      // single fp16
__device__ __half g_AOh[MTOT*EMBED], g_AOl[MTOT*EMBED];

// ---------------- helpers ---------------------------------------------------
__device__ __forceinline__ uint32_t smem_u32(const void* p) {
    uint32_t a;
    asm("{ .reg .u64 t; cvta.to.shared.u64 t, %1; cvt.u32.u64 %0, t; }"
        : "=r"(a) : "l"(p));
    return a;
}
__device__ __forceinline__ void ldsm4(uint32_t addr, uint32_t* r) {
    asm volatile("ldmatrix.sync.aligned.m8n8.x4.shared.b16 {%0,%1,%2,%3}, [%4];"
        : "=r"(r[0]), "=r"(r[1]), "=r"(r[2]), "=r"(r[3]) : "r"(addr));
}
__device__ __forceinline__ void ldsm4t(uint32_t addr, uint32_t* r) {
    asm volatile("ldmatrix.sync.aligned.m8n8.x4.trans.shared.b16 {%0,%1,%2,%3}, [%4];"
        : "=r"(r[0]), "=r"(r[1]), "=r"(r[2]), "=r"(r[3]) : "r"(addr));
}
__device__ __forceinline__ void mma_f16(float* d, const uint32_t* a, const uint32_t* b) {
    asm volatile(
        "mma.sync.aligned.m16n8k16.row.col.f32.f16.f16.f32 "
        "{%0,%1,%2,%3},{%4,%5,%6,%7},{%8,%9},{%0,%1,%2,%3};"
        : "+f"(d[0]), "+f"(d[1]), "+f"(d[2]), "+f"(d[3])
        : "r"(a[0]), "r"(a[1]), "r"(a[2]), "r"(a[3]), "r"(b[0]), "r"(b[1]));
}
__device__ __forceinline__ void cp16(uint32_t s, const void* g) {
    asm volatile("cp.async.cg.shared.global [%0], [%1], 16;" :: "r"(s), "l"(g));
}
#define CP_COMMIT() asm volatile("cp.async.commit_group;" ::: "memory")
#define CP_WAIT0()  asm volatile("cp.async.wait_group 0;" ::: "memory")
#define CP_WAIT1()  asm volatile("cp.async.wait_group 1;" ::: "memory")

__device__ __forceinline__ uint32_t h2bits(__half2 h) {
    return *reinterpret_cast<uint32_t*>(&h);
}
__device__ __forceinline__ uint32_t hpack(float x, float y) {
    return h2bits(__floats2half2_rn(x, y));
}
__device__ __forceinline__ uint32_t lpack(float x, float y) {
    __half hx = __float2half_rn(x), hy = __float2half_rn(y);
    float rx = x - __half2float(hx), ry = y - __half2float(hy);
    return h2bits(__floats2half2_rn(rx, ry));
}
// 128B-row swizzle: 16B chunk XOR row%8
__device__ __forceinline__ uint32_t swz128(int row, int chunk) {
    return (uint32_t)(row * 128 + ((chunk ^ (row & 7)) << 4));
}
// 32B-row GEMM tile swizzle: chunk(0/1) XOR (row>>2)&1
__device__ __forceinline__ uint32_t tile_off(int r, int chunk) {
    return (uint32_t)(r * 32 + ((chunk ^ ((r >> 2) & 1)) << 4));
}

// ---------------------------------------------------------------------------
// Pre-kernels
// ---------------------------------------------------------------------------
__global__ void convert_hl_kernel(const float* __restrict__ S,
                                  __half* __restrict__ Dh,
                                  __half* __restrict__ Dl)
{
    int i = blockIdx.x * blockDim.x + threadIdx.x;
    float4 v = ((const float4*)S)[i];
    uint2 h, l;
    h.x = hpack(v.x, v.y); h.y = hpack(v.z, v.w);
    l.x = lpack(v.x, v.y); l.y = lpack(v.z, v.w);
    ((uint2*)Dh)[i] = h;
    ((uint2*)Dl)[i] = l;
}

// src[K][N] f32 -> dst[N][K] single fp16
__global__ void transpose_h_kernel(const float* __restrict__ S,
                                   __half* __restrict__ D, int K, int N)
{
    __shared__ float t[32][33];
    int bx = blockIdx.x * 32;
    int by = blockIdx.y * 32;
    int tx = threadIdx.x, ty = threadIdx.y;
#pragma unroll
    for (int j = 0; j < 32; j += 8)
        t[ty + j][tx] = S[(size_t)(by + ty + j) * N + bx + tx];
    __syncthreads();
#pragma unroll
    for (int j = 0; j < 32; j += 8)
        D[(size_t)(bx + ty + j) * K + by + tx] = __float2half_rn(t[tx][ty + j]);
}

// ---------------------------------------------------------------------------
// fp16 2-term GEMM: C = (Ah+Al)[M,1024] @ B[N,1024]^T + bias
// Small-CTA: 128 thr, CTA 128x64, warp 64x32, BK=16, 3-stage ring, 4 CTA/SM.
// MODE 0: scatter Q(single, scaled) / K,V (single) head-major   MODE 1: f32 C
// ---------------------------------------------------------------------------
#define STG_B     10240                 // Ah 4K | Al 4K | B 2K
#define GEMM_SMEM (3 * STG_B)           // 30720
#define NIT16     (GEMM_K / 16)         // 64

template<int MODE>
__global__ __launch_bounds__(128, 4) void gemm_f16_kernel(
    const __half* __restrict__ Ah, const __half* __restrict__ Al,
    const __half* __restrict__ B,
    const float* __restrict__ bias, float* __restrict__ C, int Nfull)
{
    extern __shared__ __align__(16) uint8_t smg[];

    const int tid  = threadIdx.x;
    const int lane = tid & 31;
    const int wid  = tid >> 5;
    const int wm   = wid >> 1;
    const int wn   = wid & 1;
    const int m0   = blockIdx.y * 128;
    const int n0   = blockIdx.x * 64;
    const uint32_t uSm = smem_u32(smg);

    const int ar0 = tid >> 1,  ac0 = tid & 1;
    const int ar1 = (tid + 128) >> 1;
    const int br  = tid >> 1,  bc  = tid & 1;
    const uint32_t aof0 = tile_off(ar0, ac0);
    const uint32_t aof1 = tile_off(ar1, ac0);
    const uint32_t bof  = tile_off(br, bc);

    auto issue = [&](int buf, int it) {
        const int k0 = it * 16;
        const uint32_t s = uSm + buf * STG_B;
        cp16(s + aof0,        Ah + (size_t)(m0 + ar0) * GEMM_K + k0 + ac0 * 8);
        cp16(s + aof1,        Ah + (size_t)(m0 + ar1) * GEMM_K + k0 + ac0 * 8);
        cp16(s + 4096 + aof0, Al + (size_t)(m0 + ar0) * GEMM_K + k0 + ac0 * 8);
        cp16(s + 4096 + aof1, Al + (size_t)(m0 + ar1) * GEMM_K + k0 + ac0 * 8);
        cp16(s + 8192 + bof,  B  + (size_t)(n0 + br) * GEMM_K + k0 + bc * 8);
    };

    float acc[4][4][4];
#pragma unroll
    for (int t = 0; t < 4; t++)
#pragma unroll
        for (int u = 0; u < 4; u++)
#pragma unroll
            for (int e = 0; e < 4; e++) acc[t][u][e] = 0.f;

    issue(0, 0); CP_COMMIT();
    issue(1, 1); CP_COMMIT();

    const int arow = wm * 64 + (lane & 15);
    const int achk = lane >> 4;
    const int brow_base = wn * 32 + (lane & 7) + ((lane >> 4) << 3);
    const int bchk = (lane >> 3) & 1;

    for (int it = 0; it < NIT16; ++it) {
        if (it >= NIT16 - 1) { CP_WAIT0(); } else { CP_WAIT1(); }
        __syncthreads();
        if (it + 2 < NIT16) { issue((it + 2) % 3, it + 2); CP_COMMIT(); }

        const uint32_t s   = uSm + (it % 3) * STG_B;
        const uint32_t bAh = s, bAl = s + 4096, bB = s + 8192;

        uint32_t aH[4][4], aL[4][4], bF[8];
#pragma unroll
        for (int t = 0; t < 4; t++) {
            const uint32_t off = tile_off(arow + t * 16, achk);
            ldsm4(bAh + off, aH[t]);
            ldsm4(bAl + off, aL[t]);
        }
#pragma unroll
        for (int p = 0; p < 2; p++)
            ldsm4(bB + tile_off(brow_base + p * 16, bchk), &bF[p * 4]);

#pragma unroll
        for (int t = 0; t < 4; t++)
#pragma unroll
            for (int u = 0; u < 4; u++)
                mma_f16(acc[t][u], aH[t], &bF[(u >> 1) * 4 + (u & 1) * 2]);
#pragma unroll
        for (int t = 0; t < 4; t++)
#pragma unroll
            for (int u = 0; u < 4; u++)
                mma_f16(acc[t][u], aL[t], &bF[(u >> 1) * 4 + (u & 1) * 2]);
    }

    // ---- epilogue ----------------------------------------------------------
    const int mwarp = m0 + wm * 64;
    const int nwarp = n0 + wn * 32;
    const int g = lane >> 2, q = lane & 3;
#pragma unroll
    for (int u = 0; u < 4; u++) {
        const int n = nwarp + u * 8 + 2 * q;
        const float2 bv = *(const float2*)(bias + n);
#pragma unroll
        for (int t = 0; t < 4; t++) {
            const int m = mwarp + t * 16 + g;
            float2 v0 = make_float2(acc[t][u][0] + bv.x, acc[t][u][1] + bv.y);
            float2 v1 = make_float2(acc[t][u][2] + bv.x, acc[t][u][3] + bv.y);
            if (MODE == 1) {
                *(float2*)(C + (size_t)m * Nfull + n)       = v0;
                *(float2*)(C + (size_t)(m + 8) * Nfull + n) = v1;
            } else {
                const int which = n >> 10;
                const int e = n & 1023;
                const int h = e >> 6;
                const int d = e & 63;
                const int b  = m >> 11;
                const size_t base = (((size_t)(b * NHEADS + h)) * NSEQ) * HDIM + d;
                const size_t o0 = base + (size_t)(m & 2047) * HDIM;
                const size_t o1 = base + (size_t)((m + 8) & 2047) * HDIM;
                if (which == 0) {
                    v0.x *= ATTN_SCALE; v0.y *= ATTN_SCALE;
                    v1.x *= ATTN_SCALE; v1.y *= ATTN_SCALE;
                    *(uint32_t*)(g_Q + o0) = hpack(v0.x, v0.y);
                    *(uint32_t*)(g_Q + o1) = hpack(v1.x, v1.y);
                } else {
                    __half* dst = (which == 1) ? g_K : g_V;
                    *(uint32_t*)(dst + o0) = hpack(v0.x, v0.y);
                    *(uint32_t*)(dst + o1) = hpack(v1.x, v1.y);
                }
            }
        }
    }
}

// ---------------------------------------------------------------------------
// Flash attention v5: all-single fp16 MMAs (Q, K, P, V single; AO hi/lo out).
// 256 thr, 128 q-rows, kv tile 64, Q resident (16KB), 2-stage KV (2x16KB).
// ---------------------------------------------------------------------------
#define FLASH_SMEM (16384 + 2*16384)   // 48KB

__global__ __launch_bounds__(256, 2) void flash_mma_v5()
{
    extern __shared__ __align__(16) uint8_t sb[];
    const uint32_t uQ = smem_u32(sb);

    const int tid  = threadIdx.x;
    const int lane = tid & 31;
    const int wid  = tid >> 5;
    const int mt   = blockIdx.x;       // q tile (0..15)
    const int bh   = blockIdx.y;       // 0..31

    const size_t kvbase = (size_t)bh * NSEQ * HDIM;
    const __half* Qg = g_Q + kvbase + (size_t)mt * 128 * HDIM;

    // Q load: 128 rows x 8 chunks (128B rows), single
    {
        const int r = tid >> 1;
        const int cb = (tid & 1) * 4;
#pragma unroll
        for (int c = 0; c < 4; c++)
            cp16(uQ + swz128(r, cb + c), Qg + (size_t)r * HDIM + (cb + c) * 8);
    }

    auto issue_kv = [&](int t, int buf) {
        const uint32_t base = uQ + 16384 + buf * 16384;
        const __half* Ks = g_K + kvbase + (size_t)t * 64 * HDIM;
        const __half* Vs = g_V + kvbase + (size_t)t * 64 * HDIM;
#pragma unroll
        for (int i = 0; i < 2; i++) {
            const int id = tid + i * 256;       // 0..511
            const int r = id >> 3, c = id & 7;
            const uint32_t off = swz128(r, c);
            const size_t src = (size_t)r * HDIM + c * 8;
            cp16(base + off,        Ks + src);
            cp16(base + 8192 + off, Vs + src);
        }
    };

    issue_kv(0, 0);
    CP_COMMIT();

    float of[8][4];
#pragma unroll
    for (int u = 0; u < 8; u++)
#pragma unroll
        for (int e = 0; e < 4; e++) of[u][e] = 0.f;
    float m0 = -1e30f, m1 = -1e30f, l0 = 0.f, l1 = 0.f;

    const int qrow = wid * 16 + (lane & 15);
    const int qsel = lane >> 4;
    const int brow = (lane & 7) + ((lane >> 4) << 3);
    const int bsel = (lane >> 3) & 1;
    const int vrow_l = lane & 15;
    const int vsel   = lane >> 4;

    for (int t = 0; t < NSEQ / 64; t++) {
        CP_WAIT0();
        __syncthreads();
        if (t + 1 < NSEQ / 64) { issue_kv(t + 1, (t + 1) & 1); CP_COMMIT(); }

        const uint32_t kvb = uQ + 16384 + (t & 1) * 16384;
        const uint32_t uK = kvb, uV = kvb + 8192;

        // ---- S = Q @ K^T (single fp16) ------------------------------------
        float sf[8][4];
#pragma unroll
        for (int u = 0; u < 8; u++)
#pragma unroll
            for (int e = 0; e < 4; e++) sf[u][e] = 0.f;

#pragma unroll
        for (int kc = 0; kc < 4; kc++) {
            uint32_t qf[4];
            ldsm4(uQ + swz128(qrow, 2 * kc + qsel), qf);
            uint32_t bb[16];
#pragma unroll
            for (int nb = 0; nb < 4; nb++)
                ldsm4(uK + swz128(nb * 16 + brow, 2 * kc + bsel), &bb[nb * 4]);
#pragma unroll
            for (int u = 0; u < 8; u++)
                mma_f16(sf[u], qf, &bb[(u >> 1) * 4 + (u & 1) * 2]);
        }

        // ---- online softmax ----------------------------------------------
        {
            float mx0 = -1e30f, mx1 = -1e30f;
#pragma unroll
            for (int u = 0; u < 8; u++) {
                mx0 = fmaxf(mx0, fmaxf(sf[u][0], sf[u][1]));
                mx1 = fmaxf(mx1, fmaxf(sf[u][2], sf[u][3]));
            }
            mx0 = fmaxf(mx0, __shfl_xor_sync(0xffffffffu, mx0, 1));
            mx0 = fmaxf(mx0, __shfl_xor_sync(0xffffffffu, mx0, 2));
            mx1 = fmaxf(mx1, __shfl_xor_sync(0xffffffffu, mx1, 1));
            mx1 = fmaxf(mx1, __shfl_xor_sync(0xffffffffu, mx1, 2));

            float mn0 = fmaxf(m0, mx0), mn1 = fmaxf(m1, mx1);
            float c0 = __expf(m0 - mn0), c1 = __expf(m1 - mn1);
            m0 = mn0; m1 = mn1;
            float s0 = 0.f, s1 = 0.f;
#pragma unroll
            for (int u = 0; u < 8; u++) {
                float p0 = __expf(sf[u][0] - mn0);
                float p1 = __expf(sf[u][1] - mn0);
                float p2 = __expf(sf[u][2] - mn1);
                float p3 = __expf(sf[u][3] - mn1);
                s0 += p0 + p1; s1 += p2 + p3;
                sf[u][0] = p0; sf[u][1] = p1; sf[u][2] = p2; sf[u][3] = p3;
            }
            s0 += __shfl_xor_sync(0xffffffffu, s0, 1);
            s0 += __shfl_xor_sync(0xffffffffu, s0, 2);
            s1 += __shfl_xor_sync(0xffffffffu, s1, 1);
            s1 += __shfl_xor_sync(0xffffffffu, s1, 2);
            l0 = l0 * c0 + s0; l1 = l1 * c1 + s1;
#pragma unroll
            for (int u = 0; u < 8; u++) {
                of[u][0] *= c0; of[u][1] *= c0;
                of[u][2] *= c1; of[u][3] *= c1;
            }
        }

        // ---- P frags (single fp16) ----------------------------------------
        uint32_t pF[4][4];
#pragma unroll
        for (int kc = 0; kc < 4; kc++) {
            pF[kc][0] = hpack(sf[2*kc][0],   sf[2*kc][1]);
            pF[kc][1] = hpack(sf[2*kc][2],   sf[2*kc][3]);
            pF[kc][2] = hpack(sf[2*kc+1][0], sf[2*kc+1][1]);
            pF[kc][3] = hpack(sf[2*kc+1][2], sf[2*kc+1][3]);
        }

        // ---- O += P @ V (single fp16; V via ldmatrix.trans) ---------------
#pragma unroll
        for (int kc = 0; kc < 4; kc++) {
            uint32_t vv[16];
            const int row = 16 * kc + vrow_l;
#pragma unroll
            for (int vp = 0; vp < 4; vp++)
                ldsm4t(uV + swz128(row, 2 * vp + vsel), &vv[vp * 4]);
#pragma unroll
            for (int u = 0; u < 8; u++)
                mma_f16(of[u], pF[kc], &vv[(u >> 1) * 4 + (u & 1) * 2]);
        }
    }

    // ---- epilogue: normalize, write AO as fp16 hi/lo [B*N, E] --------------
    const float inv0 = __fdividef(1.f, l0);
    const float inv1 = __fdividef(1.f, l1);
    const int b = bh >> 4, h = bh & 15;
    const int g = lane >> 2, q = lane & 3;
    const int nrow = mt * 128 + wid * 16 + g;
    const size_t r0 = ((size_t)(b * NSEQ + nrow)) * EMBED + h * HDIM;
    const size_t r1 = r0 + (size_t)8 * EMBED;
#pragma unroll
    for (int u = 0; u < 8; u++) {
        const int col = 8 * u + 2 * q;
        float x0 = of[u][0] * inv0, y0 = of[u][1] * inv0;
        float x1 = of[u][2] * inv1, y1 = of[u][3] * inv1;
        *(uint32_t*)(g_AOh + r0 + col) = hpack(x0, y0);
        *(uint32_t*)(g_AOl + r0 + col) = lpack(x0, y0);
        *(uint32_t*)(g_AOh + r1 + col) = hpack(x1, y1);
        *(uint32_t*)(g_AOl + r1 + col) = lpack(x1, y1);
    }
}

// ---------------------------------------------------------------------------
extern "C" void kernel_launch(void* const* d_in, const int* in_sizes, int n_in,
                              void* d_out, int out_size)
{
    const float* x     = (const float*)d_in[0];
    const float* W_qkv = (const float*)d_in[1];
    const float* b_qkv = (const float*)d_in[2];
    const float* W_out = (const float*)d_in[3];
    const float* b_out = (const float*)d_in[4];
    float* out = (float*)d_out;

    __half *xh, *xl, *wq, *wo, *aoh, *aol;
    cudaGetSymbolAddress((void**)&xh,  g_Xh);
    cudaGetSymbolAddress((void**)&xl,  g_Xl);
    cudaGetSymbolAddress((void**)&wq,  g_Wq);
    cudaGetSymbolAddress((void**)&wo,  g_Wo);
    cudaGetSymbolAddress((void**)&aoh, g_AOh);
    cudaGetSymbolAddress((void**)&aol, g_AOl);

    cudaFuncSetAttribute(flash_mma_v5,
                         cudaFuncAttributeMaxDynamicSharedMemorySize, FLASH_SMEM);
    cudaFuncSetAttribute(gemm_f16_kernel<0>,
                         cudaFuncAttributeMaxDynamicSharedMemorySize, GEMM_SMEM);
    cudaFuncSetAttribute(gemm_f16_kernel<1>,
                         cudaFuncAttributeMaxDynamicSharedMemorySize, GEMM_SMEM);

    // 0) one-time conversions
    convert_hl_kernel<<<(MTOT * EMBED / 4) / 256, 256>>>(x, xh, xl);
    transpose_h_kernel<<<dim3(3*EMBED/32, EMBED/32), dim3(32, 8)>>>(W_qkv, wq, EMBED, 3*EMBED);
    transpose_h_kernel<<<dim3(EMBED/32,   EMBED/32), dim3(32, 8)>>>(W_out, wo, EMBED, EMBED);

    // 1) QKV projection -> Q/K/V single fp16 head-major (Q pre-scaled)
    gemm_f16_kernel<0><<<dim3(3*EMBED/64, MTOT/128), 128, GEMM_SMEM>>>(
        xh, xl, wq, b_qkv, nullptr, 3*EMBED);

    // 2) flash attention -> AO fp16 hi/lo
    flash_mma_v5<<<dim3(NSEQ/128, NB*NHEADS), 256, FLASH_SMEM>>>();

    // 3) output projection -> d_out (fp32)
    gemm_f16_kernel<1><<<dim3(EMBED/64, MTOT/128), 128, GEMM_SMEM>>>(
        aoh, aol, wo, b_out, out, EMBED);
}

// round 16
// speedup vs baseline: 2.4277x; 1.3606x over previous
#include <cuda_runtime.h>
#include <cuda_fp16.h>
#include <cstdint>
#include <math.h>

#define EMBED  1024
#define NHEADS 16
#define HDIM   64
#define NB     2
#define NSEQ   2048
#define MTOT   (NB*NSEQ)          // 4096
#define GEMM_K 1024
#define ATTN_SCALE 0.125f

// ---------------- scratch (__device__ globals) ------------------------------
__device__ __half g_X[MTOT*EMBED];               // x single fp16
__device__ __half g_Wq[3*EMBED*EMBED];           // W_qkv^T single fp16
__device__ __half g_Wo[EMBED*EMBED];             // W_out^T single fp16
__device__ __half g_Q[NB*NHEADS*NSEQ*HDIM];      // single fp16 (scaled)
__device__ __half g_K[NB*NHEADS*NSEQ*HDIM];
__device__ __half g_V[NB*NHEADS*NSEQ*HDIM];
__device__ __half g_AO[MTOT*EMBED];              // attention out single fp16

// ---------------- helpers ---------------------------------------------------
__device__ __forceinline__ uint32_t smem_u32(const void* p) {
    uint32_t a;
    asm("{ .reg .u64 t; cvta.to.shared.u64 t, %1; cvt.u32.u64 %0, t; }"
        : "=r"(a) : "l"(p));
    return a;
}
__device__ __forceinline__ void ldsm4(uint32_t addr, uint32_t* r) {
    asm volatile("ldmatrix.sync.aligned.m8n8.x4.shared.b16 {%0,%1,%2,%3}, [%4];"
        : "=r"(r[0]), "=r"(r[1]), "=r"(r[2]), "=r"(r[3]) : "r"(addr));
}
__device__ __forceinline__ void ldsm4t(uint32_t addr, uint32_t* r) {
    asm volatile("ldmatrix.sync.aligned.m8n8.x4.trans.shared.b16 {%0,%1,%2,%3}, [%4];"
        : "=r"(r[0]), "=r"(r[1]), "=r"(r[2]), "=r"(r[3]) : "r"(addr));
}
__device__ __forceinline__ void mma_f16(float* d, const uint32_t* a, const uint32_t* b) {
    asm volatile(
        "mma.sync.aligned.m16n8k16.row.col.f32.f16.f16.f32 "
        "{%0,%1,%2,%3},{%4,%5,%6,%7},{%8,%9},{%0,%1,%2,%3};"
        : "+f"(d[0]), "+f"(d[1]), "+f"(d[2]), "+f"(d[3])
        : "r"(a[0]), "r"(a[1]), "r"(a[2]), "r"(a[3]), "r"(b[0]), "r"(b[1]));
}
__device__ __forceinline__ void cp16(uint32_t s, const void* g) {
    asm volatile("cp.async.cg.shared.global [%0], [%1], 16;" :: "r"(s), "l"(g));
}
#define CP_COMMIT() asm volatile("cp.async.commit_group;" ::: "memory")
#define CP_WAIT0()  asm volatile("cp.async.wait_group 0;" ::: "memory")
#define CP_WAIT1()  asm volatile("cp.async.wait_group 1;" ::: "memory")

__device__ __forceinline__ uint32_t h2bits(__half2 h) {
    return *reinterpret_cast<uint32_t*>(&h);
}
__device__ __forceinline__ uint32_t hpack(float x, float y) {
    return h2bits(__floats2half2_rn(x, y));
}
// 128B-row swizzle: 16B chunk XOR row%8
__device__ __forceinline__ uint32_t swz128(int row, int chunk) {
    return (uint32_t)(row * 128 + ((chunk ^ (row & 7)) << 4));
}
// 32B-row GEMM tile swizzle: chunk(0/1) XOR (row>>2)&1
__device__ __forceinline__ uint32_t tile_off(int r, int chunk) {
    return (uint32_t)(r * 32 + ((chunk ^ ((r >> 2) & 1)) << 4));
}

// ---------------------------------------------------------------------------
// Pre-kernels
// ---------------------------------------------------------------------------
__global__ void convert_h_kernel(const float* __restrict__ S,
                                 __half* __restrict__ D)
{
    int i = blockIdx.x * blockDim.x + threadIdx.x;   // float4 index
    float4 v = ((const float4*)S)[i];
    uint2 h;
    h.x = hpack(v.x, v.y); h.y = hpack(v.z, v.w);
    ((uint2*)D)[i] = h;
}

// src[K][N] f32 -> dst[N][K] single fp16
__global__ void transpose_h_kernel(const float* __restrict__ S,
                                   __half* __restrict__ D, int K, int N)
{
    __shared__ float t[32][33];
    int bx = blockIdx.x * 32;
    int by = blockIdx.y * 32;
    int tx = threadIdx.x, ty = threadIdx.y;
#pragma unroll
    for (int j = 0; j < 32; j += 8)
        t[ty + j][tx] = S[(size_t)(by + ty + j) * N + bx + tx];
    __syncthreads();
#pragma unroll
    for (int j = 0; j < 32; j += 8)
        D[(size_t)(bx + ty + j) * K + by + tx] = __float2half_rn(t[tx][ty + j]);
}

// ---------------------------------------------------------------------------
// fp16 single-term GEMM: C = A[M,1024] @ B[N,1024]^T + bias
// Small-CTA: 128 thr, CTA 128x64, warp 64x32, BK=16, 3-stage ring, 4 CTA/SM.
// MODE 0: scatter Q(scaled)/K/V single fp16 head-major    MODE 1: f32 C
// ---------------------------------------------------------------------------
#define STG_B     6144                  // A 4K | B 2K
#define GEMM_SMEM (3 * STG_B)           // 18432
#define NIT16     (GEMM_K / 16)         // 64

template<int MODE>
__global__ __launch_bounds__(128, 4) void gemm_f16_kernel(
    const __half* __restrict__ A, const __half* __restrict__ B,
    const float* __restrict__ bias, float* __restrict__ C, int Nfull)
{
    extern __shared__ __align__(16) uint8_t smg[];

    const int tid  = threadIdx.x;
    const int lane = tid & 31;
    const int wid  = tid >> 5;
    const int wm   = wid >> 1;
    const int wn   = wid & 1;
    const int m0   = blockIdx.y * 128;
    const int n0   = blockIdx.x * 64;
    const uint32_t uSm = smem_u32(smg);

    const int ar0 = tid >> 1,  ac0 = tid & 1;
    const int ar1 = (tid + 128) >> 1;
    const int br  = tid >> 1,  bc  = tid & 1;
    const uint32_t aof0 = tile_off(ar0, ac0);
    const uint32_t aof1 = tile_off(ar1, ac0);
    const uint32_t bof  = tile_off(br, bc);

    auto issue = [&](int buf, int it) {
        const int k0 = it * 16;
        const uint32_t s = uSm + buf * STG_B;
        cp16(s + aof0,       A + (size_t)(m0 + ar0) * GEMM_K + k0 + ac0 * 8);
        cp16(s + aof1,       A + (size_t)(m0 + ar1) * GEMM_K + k0 + ac0 * 8);
        cp16(s + 4096 + bof, B + (size_t)(n0 + br) * GEMM_K + k0 + bc * 8);
    };

    float acc[4][4][4];
#pragma unroll
    for (int t = 0; t < 4; t++)
#pragma unroll
        for (int u = 0; u < 4; u++)
#pragma unroll
            for (int e = 0; e < 4; e++) acc[t][u][e] = 0.f;

    issue(0, 0); CP_COMMIT();
    issue(1, 1); CP_COMMIT();

    const int arow = wm * 64 + (lane & 15);
    const int achk = lane >> 4;
    const int brow_base = wn * 32 + (lane & 7) + ((lane >> 4) << 3);
    const int bchk = (lane >> 3) & 1;

    for (int it = 0; it < NIT16; ++it) {
        if (it >= NIT16 - 1) { CP_WAIT0(); } else { CP_WAIT1(); }
        __syncthreads();
        if (it + 2 < NIT16) { issue((it + 2) % 3, it + 2); CP_COMMIT(); }

        const uint32_t s  = uSm + (it % 3) * STG_B;
        const uint32_t bA = s, bB = s + 4096;

        uint32_t aF[4][4], bF[8];
#pragma unroll
        for (int t = 0; t < 4; t++)
            ldsm4(bA + tile_off(arow + t * 16, achk), aF[t]);
#pragma unroll
        for (int p = 0; p < 2; p++)
            ldsm4(bB + tile_off(brow_base + p * 16, bchk), &bF[p * 4]);

#pragma unroll
        for (int t = 0; t < 4; t++)
#pragma unroll
            for (int u = 0; u < 4; u++)
                mma_f16(acc[t][u], aF[t], &bF[(u >> 1) * 4 + (u & 1) * 2]);
    }

    // ---- epilogue ----------------------------------------------------------
    const int mwarp = m0 + wm * 64;
    const int nwarp = n0 + wn * 32;
    const int g = lane >> 2, q = lane & 3;
#pragma unroll
    for (int u = 0; u < 4; u++) {
        const int n = nwarp + u * 8 + 2 * q;
        const float2 bv = *(const float2*)(bias + n);
#pragma unroll
        for (int t = 0; t < 4; t++) {
            const int m = mwarp + t * 16 + g;
            float2 v0 = make_float2(acc[t][u][0] + bv.x, acc[t][u][1] + bv.y);
            float2 v1 = make_float2(acc[t][u][2] + bv.x, acc[t][u][3] + bv.y);
            if (MODE == 1) {
                *(float2*)(C + (size_t)m * Nfull + n)       = v0;
                *(float2*)(C + (size_t)(m + 8) * Nfull + n) = v1;
            } else {
                const int which = n >> 10;
                const int e = n & 1023;
                const int h = e >> 6;
                const int d = e & 63;
                const int b  = m >> 11;
                const size_t base = (((size_t)(b * NHEADS + h)) * NSEQ) * HDIM + d;
                const size_t o0 = base + (size_t)(m & 2047) * HDIM;
                const size_t o1 = base + (size_t)((m + 8) & 2047) * HDIM;
                if (which == 0) {
                    v0.x *= ATTN_SCALE; v0.y *= ATTN_SCALE;
                    v1.x *= ATTN_SCALE; v1.y *= ATTN_SCALE;
                    *(uint32_t*)(g_Q + o0) = hpack(v0.x, v0.y);
                    *(uint32_t*)(g_Q + o1) = hpack(v1.x, v1.y);
                } else {
                    __half* dst = (which == 1) ? g_K : g_V;
                    *(uint32_t*)(dst + o0) = hpack(v0.x, v0.y);
                    *(uint32_t*)(dst + o1) = hpack(v1.x, v1.y);
                }
            }
        }
    }
}

// ---------------------------------------------------------------------------
// Flash attention v5 (r15): all-single fp16 MMAs; AO now single fp16 out.
// 256 thr, 128 q-rows, kv tile 64, Q resident (16KB), 2-stage KV (2x16KB).
// ---------------------------------------------------------------------------
#define FLASH_SMEM (16384 + 2*16384)   // 48KB

__global__ __launch_bounds__(256, 2) void flash_mma_v5()
{
    extern __shared__ __align__(16) uint8_t sb[];
    const uint32_t uQ = smem_u32(sb);

    const int tid  = threadIdx.x;
    const int lane = tid & 31;
    const int wid  = tid >> 5;
    const int mt   = blockIdx.x;       // q tile (0..15)
    const int bh   = blockIdx.y;       // 0..31

    const size_t kvbase = (size_t)bh * NSEQ * HDIM;
    const __half* Qg = g_Q + kvbase + (size_t)mt * 128 * HDIM;

    {
        const int r = tid >> 1;
        const int cb = (tid & 1) * 4;
#pragma unroll
        for (int c = 0; c < 4; c++)
            cp16(uQ + swz128(r, cb + c), Qg + (size_t)r * HDIM + (cb + c) * 8);
    }

    auto issue_kv = [&](int t, int buf) {
        const uint32_t base = uQ + 16384 + buf * 16384;
        const __half* Ks = g_K + kvbase + (size_t)t * 64 * HDIM;
        const __half* Vs = g_V + kvbase + (size_t)t * 64 * HDIM;
#pragma unroll
        for (int i = 0; i < 2; i++) {
            const int id = tid + i * 256;
            const int r = id >> 3, c = id & 7;
            const uint32_t off = swz128(r, c);
            const size_t src = (size_t)r * HDIM + c * 8;
            cp16(base + off,        Ks + src);
            cp16(base + 8192 + off, Vs + src);
        }
    };

    issue_kv(0, 0);
    CP_COMMIT();

    float of[8][4];
#pragma unroll
    for (int u = 0; u < 8; u++)
#pragma unroll
        for (int e = 0; e < 4; e++) of[u][e] = 0.f;
    float m0 = -1e30f, m1 = -1e30f, l0 = 0.f, l1 = 0.f;

    const int qrow = wid * 16 + (lane & 15);
    const int qsel = lane >> 4;
    const int brow = (lane & 7) + ((lane >> 4) << 3);
    const int bsel = (lane >> 3) & 1;
    const int vrow_l = lane & 15;
    const int vsel   = lane >> 4;

    for (int t = 0; t < NSEQ / 64; t++) {
        CP_WAIT0();
        __syncthreads();
        if (t + 1 < NSEQ / 64) { issue_kv(t + 1, (t + 1) & 1); CP_COMMIT(); }

        const uint32_t kvb = uQ + 16384 + (t & 1) * 16384;
        const uint32_t uK = kvb, uV = kvb + 8192;

        // ---- S = Q @ K^T (single fp16) ------------------------------------
        float sf[8][4];
#pragma unroll
        for (int u = 0; u < 8; u++)
#pragma unroll
            for (int e = 0; e < 4; e++) sf[u][e] = 0.f;

#pragma unroll
        for (int kc = 0; kc < 4; kc++) {
            uint32_t qf[4];
            ldsm4(uQ + swz128(qrow, 2 * kc + qsel), qf);
            uint32_t bb[16];
#pragma unroll
            for (int nb = 0; nb < 4; nb++)
                ldsm4(uK + swz128(nb * 16 + brow, 2 * kc + bsel), &bb[nb * 4]);
#pragma unroll
            for (int u = 0; u < 8; u++)
                mma_f16(sf[u], qf, &bb[(u >> 1) * 4 + (u & 1) * 2]);
        }

        // ---- online softmax ----------------------------------------------
        {
            float mx0 = -1e30f, mx1 = -1e30f;
#pragma unroll
            for (int u = 0; u < 8; u++) {
                mx0 = fmaxf(mx0, fmaxf(sf[u][0], sf[u][1]));
                mx1 = fmaxf(mx1, fmaxf(sf[u][2], sf[u][3]));
            }
            mx0 = fmaxf(mx0, __shfl_xor_sync(0xffffffffu, mx0, 1));
            mx0 = fmaxf(mx0, __shfl_xor_sync(0xffffffffu, mx0, 2));
            mx1 = fmaxf(mx1, __shfl_xor_sync(0xffffffffu, mx1, 1));
            mx1 = fmaxf(mx1, __shfl_xor_sync(0xffffffffu, mx1, 2));

            float mn0 = fmaxf(m0, mx0), mn1 = fmaxf(m1, mx1);
            float c0 = __expf(m0 - mn0), c1 = __expf(m1 - mn1);
            m0 = mn0; m1 = mn1;
            float s0 = 0.f, s1 = 0.f;
#pragma unroll
            for (int u = 0; u < 8; u++) {
                float p0 = __expf(sf[u][0] - mn0);
                float p1 = __expf(sf[u][1] - mn0);
                float p2 = __expf(sf[u][2] - mn1);
                float p3 = __expf(sf[u][3] - mn1);
                s0 += p0 + p1; s1 += p2 + p3;
                sf[u][0] = p0; sf[u][1] = p1; sf[u][2] = p2; sf[u][3] = p3;
            }
            s0 += __shfl_xor_sync(0xffffffffu, s0, 1);
            s0 += __shfl_xor_sync(0xffffffffu, s0, 2);
            s1 += __shfl_xor_sync(0xffffffffu, s1, 1);
            s1 += __shfl_xor_sync(0xffffffffu, s1, 2);
            l0 = l0 * c0 + s0; l1 = l1 * c1 + s1;
#pragma unroll
            for (int u = 0; u < 8; u++) {
                of[u][0] *= c0; of[u][1] *= c0;
                of[u][2] *= c1; of[u][3] *= c1;
            }
        }

        // ---- P frags (single fp16) ----------------------------------------
        uint32_t pF[4][4];
#pragma unroll
        for (int kc = 0; kc < 4; kc++) {
            pF[kc][0] = hpack(sf[2*kc][0],   sf[2*kc][1]);
            pF[kc][1] = hpack(sf[2*kc][2],   sf[2*kc][3]);
            pF[kc][2] = hpack(sf[2*kc+1][0], sf[2*kc+1][1]);
            pF[kc][3] = hpack(sf[2*kc+1][2], sf[2*kc+1][3]);
        }

        // ---- O += P @ V (single fp16; V via ldmatrix.trans) ---------------
#pragma unroll
        for (int kc = 0; kc < 4; kc++) {
            uint32_t vv[16];
            const int row = 16 * kc + vrow_l;
#pragma unroll
            for (int vp = 0; vp < 4; vp++)
                ldsm4t(uV + swz128(row, 2 * vp + vsel), &vv[vp * 4]);
#pragma unroll
            for (int u = 0; u < 8; u++)
                mma_f16(of[u], pF[kc], &vv[(u >> 1) * 4 + (u & 1) * 2]);
        }
    }

    // ---- epilogue: normalize, write AO single fp16 [B*N, E] ----------------
    const float inv0 = __fdividef(1.f, l0);
    const float inv1 = __fdividef(1.f, l1);
    const int b = bh >> 4, h = bh & 15;
    const int g = lane >> 2, q = lane & 3;
    const int nrow = mt * 128 + wid * 16 + g;
    const size_t r0 = ((size_t)(b * NSEQ + nrow)) * EMBED + h * HDIM;
    const size_t r1 = r0 + (size_t)8 * EMBED;
#pragma unroll
    for (int u = 0; u < 8; u++) {
        const int col = 8 * u + 2 * q;
        *(uint32_t*)(g_AO + r0 + col) = hpack(of[u][0] * inv0, of[u][1] * inv0);
        *(uint32_t*)(g_AO + r1 + col) = hpack(of[u][2] * inv1, of[u][3] * inv1);
    }
}

// ---------------------------------------------------------------------------
extern "C" void kernel_launch(void* const* d_in, const int* in_sizes, int n_in,
                              void* d_out, int out_size)
{
    const float* x     = (const float*)d_in[0];
    const float* W_qkv = (const float*)d_in[1];
    const float* b_qkv = (const float*)d_in[2];
    const float* W_out = (const float*)d_in[3];
    const float* b_out = (const float*)d_in[4];
    float* out = (float*)d_out;

    __half *xp, *wq, *wo, *ao;
    cudaGetSymbolAddress((void**)&xp, g_X);
    cudaGetSymbolAddress((void**)&wq, g_Wq);
    cudaGetSymbolAddress((void**)&wo, g_Wo);
    cudaGetSymbolAddress((void**)&ao, g_AO);

    cudaFuncSetAttribute(flash_mma_v5,
                         cudaFuncAttributeMaxDynamicSharedMemorySize, FLASH_SMEM);
    cudaFuncSetAttribute(gemm_f16_kernel<0>,
                         cudaFuncAttributeMaxDynamicSharedMemorySize, GEMM_SMEM);
    cudaFuncSetAttribute(gemm_f16_kernel<1>,
                         cudaFuncAttributeMaxDynamicSharedMemorySize, GEMM_SMEM);

    // 0) one-time conversions
    convert_h_kernel<<<(MTOT * EMBED / 4) / 256, 256>>>(x, xp);
    transpose_h_kernel<<<dim3(3*EMBED/32, EMBED/32), dim3(32, 8)>>>(W_qkv, wq, EMBED, 3*EMBED);
    transpose_h_kernel<<<dim3(EMBED/32,   EMBED/32), dim3(32, 8)>>>(W_out, wo, EMBED, EMBED);

    // 1) QKV projection -> Q/K/V single fp16 head-major (Q pre-scaled)
    gemm_f16_kernel<0><<<dim3(3*EMBED/64, MTOT/128), 128, GEMM_SMEM>>>(
        xp, wq, b_qkv, nullptr, 3*EMBED);

    // 2) flash attention -> AO single fp16
    flash_mma_v5<<<dim3(NSEQ/128, NB*NHEADS), 256, FLASH_SMEM>>>();

    // 3) output projection -> d_out (fp32)
    gemm_f16_kernel<1><<<dim3(EMBED/64, MTOT/128), 128, GEMM_SMEM>>>(
        ao, wo, b_out, out, EMBED);
}